// round 2
// baseline (speedup 1.0000x reference)
#include <cuda_runtime.h>
#include <math_constants.h>

#define BATCH 8
#define CH    256
#define NPOS  4096      // 64*64
#define NGRP  8
#define CPG   (CH/NGRP) // 32

// ---------------- scratch (device globals; no allocation allowed) ----------------
__device__ float g_xn [(size_t)BATCH*CH*NPOS];
__device__ float g_q  [(size_t)BATCH*CH*NPOS];
__device__ float g_k  [(size_t)BATCH*CH*NPOS];
__device__ float g_v  [(size_t)BATCH*CH*NPOS];
__device__ float g_o  [(size_t)BATCH*CH*NPOS];
__device__ float g_attn[(size_t)BATCH*NPOS*NPOS];   // 512 MB

// ---------------- GroupNorm ----------------
// one block per (b, g); reduce 32*4096 = 131072 elems
__global__ void groupnorm_kernel(const float* __restrict__ x,
                                 const float* __restrict__ gamma,
                                 const float* __restrict__ beta) {
    const int GSZ = CPG * NPOS;                     // 131072
    int b = blockIdx.x / NGRP;
    int g = blockIdx.x % NGRP;
    const float* px = x    + ((size_t)b*CH + (size_t)g*CPG) * NPOS;
    float*       po = g_xn + ((size_t)b*CH + (size_t)g*CPG) * NPOS;
    int tid = threadIdx.x;

    float s = 0.f, s2 = 0.f;
    for (int i = tid; i < GSZ; i += blockDim.x) {
        float t = px[i];
        s += t; s2 += t*t;
    }
    __shared__ float rs[32], rs2[32];
    #pragma unroll
    for (int o = 16; o > 0; o >>= 1) {
        s  += __shfl_xor_sync(0xffffffffu, s,  o);
        s2 += __shfl_xor_sync(0xffffffffu, s2, o);
    }
    int lane = tid & 31, wid = tid >> 5;
    if (lane == 0) { rs[wid] = s; rs2[wid] = s2; }
    __syncthreads();
    int nw = blockDim.x >> 5;
    if (wid == 0) {
        s  = (lane < nw) ? rs[lane]  : 0.f;
        s2 = (lane < nw) ? rs2[lane] : 0.f;
        #pragma unroll
        for (int o = 16; o > 0; o >>= 1) {
            s  += __shfl_xor_sync(0xffffffffu, s,  o);
            s2 += __shfl_xor_sync(0xffffffffu, s2, o);
        }
        if (lane == 0) { rs[0] = s; rs2[0] = s2; }
    }
    __syncthreads();
    float mean = rs[0] * (1.f / GSZ);
    float var  = rs2[0] * (1.f / GSZ) - mean*mean;
    float rstd = rsqrtf(var + 1e-5f);

    for (int i = tid; i < GSZ; i += blockDim.x) {
        int c = g*CPG + i / NPOS;
        po[i] = (px[i] - mean) * rstd * gamma[c] + beta[c];
    }
}

// ---------------- generic batched SGEMM ----------------
// C[m,n] = alpha * sum_k A(k,m)*B(k,n) + bias[m] (+ residual)
// TA: A stored as [K,M] (A[k*lda+m]) else [M,K] (A[m*lda+k])
// TB: B stored as [N,K] (B[n*ldb+k]) else [K,N] (B[k*ldb+n])
// 64x64 block tile, BK=16, 256 threads, 4x4 per thread.
// All dims assumed divisible by tile sizes (true for this problem).
template<bool TA, bool TB>
__global__ void gemm_kernel(const float* __restrict__ A,
                            const float* __restrict__ B,
                            float* __restrict__ C,
                            int M, int N, int K,
                            int lda, int ldb, int ldc,
                            long long sA, long long sB, long long sC,
                            float alpha,
                            const float* __restrict__ bias,
                            const float* __restrict__ resid, long long sR)
{
    const int BM = 64, BN = 64, BK = 16;
    __shared__ float As[BK][BM+4];
    __shared__ float Bs[BK][BN+4];

    int bz = blockIdx.z;
    A += (size_t)bz * sA;
    B += (size_t)bz * sB;
    C += (size_t)bz * sC;
    const float* R = resid ? resid + (size_t)bz * sR : nullptr;

    int m0 = blockIdx.y * BM;
    int n0 = blockIdx.x * BN;
    int tid = threadIdx.x;
    int tx = tid & 15, ty = tid >> 4;

    float acc[4][4] = {};

    for (int k0 = 0; k0 < K; k0 += BK) {
        #pragma unroll
        for (int i = tid; i < BK*BM; i += 256) {
            int kk, mm;
            if (TA) { kk = i >> 6; mm = i & 63;
                      As[kk][mm] = A[(size_t)(k0+kk)*lda + (m0+mm)]; }
            else    { mm = i >> 4; kk = i & 15;
                      As[kk][mm] = A[(size_t)(m0+mm)*lda + (k0+kk)]; }
        }
        #pragma unroll
        for (int i = tid; i < BK*BN; i += 256) {
            int kk, nn;
            if (!TB) { kk = i >> 6; nn = i & 63;
                       Bs[kk][nn] = B[(size_t)(k0+kk)*ldb + (n0+nn)]; }
            else     { nn = i >> 4; kk = i & 15;
                       Bs[kk][nn] = B[(size_t)(n0+nn)*ldb + (k0+kk)]; }
        }
        __syncthreads();

        #pragma unroll
        for (int kk = 0; kk < BK; kk++) {
            float a[4], bb[4];
            #pragma unroll
            for (int i = 0; i < 4; i++) a[i]  = As[kk][ty + 16*i];
            #pragma unroll
            for (int j = 0; j < 4; j++) bb[j] = Bs[kk][tx + 16*j];
            #pragma unroll
            for (int i = 0; i < 4; i++)
                #pragma unroll
                for (int j = 0; j < 4; j++)
                    acc[i][j] += a[i] * bb[j];
        }
        __syncthreads();
    }

    #pragma unroll
    for (int i = 0; i < 4; i++) {
        int m = m0 + ty + 16*i;
        float bv = bias ? bias[m] : 0.f;
        #pragma unroll
        for (int j = 0; j < 4; j++) {
            int n = n0 + tx + 16*j;
            float val = acc[i][j] * alpha + bv;
            if (R) val += R[(size_t)m*ldc + n];
            C[(size_t)m*ldc + n] = val;
        }
    }
}

// ---------------- row softmax over attn[8,4096,4096] ----------------
__global__ void softmax_kernel(float* __restrict__ attn) {
    size_t row = blockIdx.x;
    float* p = attn + row * NPOS;
    int tid  = threadIdx.x;        // 256 threads, 16 elems each
    int lane = tid & 31, wid = tid >> 5;

    float v[16];
    float mx = -CUDART_INF_F;
    #pragma unroll
    for (int i = 0; i < 16; i++) { v[i] = p[tid + 256*i]; mx = fmaxf(mx, v[i]); }

    __shared__ float red[32];
    #pragma unroll
    for (int o = 16; o > 0; o >>= 1) mx = fmaxf(mx, __shfl_xor_sync(0xffffffffu, mx, o));
    if (lane == 0) red[wid] = mx;
    __syncthreads();
    if (wid == 0) {
        float t = (lane < 8) ? red[lane] : -CUDART_INF_F;
        #pragma unroll
        for (int o = 4; o > 0; o >>= 1) t = fmaxf(t, __shfl_xor_sync(0xffffffffu, t, o));
        if (lane == 0) red[0] = t;
    }
    __syncthreads();
    mx = red[0];

    float s = 0.f;
    #pragma unroll
    for (int i = 0; i < 16; i++) { v[i] = __expf(v[i] - mx); s += v[i]; }
    __shared__ float red2[32];
    #pragma unroll
    for (int o = 16; o > 0; o >>= 1) s += __shfl_xor_sync(0xffffffffu, s, o);
    if (lane == 0) red2[wid] = s;
    __syncthreads();
    if (wid == 0) {
        float t = (lane < 8) ? red2[lane] : 0.f;
        #pragma unroll
        for (int o = 4; o > 0; o >>= 1) t += __shfl_xor_sync(0xffffffffu, t, o);
        if (lane == 0) red2[0] = t;
    }
    __syncthreads();
    float inv = 1.f / red2[0];
    #pragma unroll
    for (int i = 0; i < 16; i++) p[tid + 256*i] = v[i] * inv;
}

// ---------------- launcher ----------------
extern "C" void kernel_launch(void* const* d_in, const int* in_sizes, int n_in,
                              void* d_out, int out_size) {
    const float* x     = (const float*)d_in[0];
    const float* gamma = (const float*)d_in[1];
    const float* beta  = (const float*)d_in[2];
    const float* wq    = (const float*)d_in[3];
    const float* bq    = (const float*)d_in[4];
    const float* wk    = (const float*)d_in[5];
    const float* bk    = (const float*)d_in[6];
    const float* wv    = (const float*)d_in[7];
    const float* bv    = (const float*)d_in[8];
    const float* wp    = (const float*)d_in[9];
    const float* bp    = (const float*)d_in[10];
    float* out = (float*)d_out;

    float *xn, *q, *k, *v, *o, *attn;
    cudaGetSymbolAddress((void**)&xn,   g_xn);
    cudaGetSymbolAddress((void**)&q,    g_q);
    cudaGetSymbolAddress((void**)&k,    g_k);
    cudaGetSymbolAddress((void**)&v,    g_v);
    cudaGetSymbolAddress((void**)&o,    g_o);
    cudaGetSymbolAddress((void**)&attn, g_attn);

    // 1. GroupNorm
    groupnorm_kernel<<<BATCH*NGRP, 1024>>>(x, gamma, beta);

    const long long sX  = (long long)CH * NPOS;        // per-batch activation stride
    const long long sAt = (long long)NPOS * NPOS;      // per-batch attn stride

    // 2. Q/K/V projections: W[256,256] (row-major, k fast) x Xn[256,4096]
    dim3 gq(NPOS/64, CH/64, BATCH);
    gemm_kernel<false,false><<<gq,256>>>(wq, xn, q, CH, NPOS, CH,
                                         CH, NPOS, NPOS, 0, sX, sX,
                                         1.f, bq, nullptr, 0);
    gemm_kernel<false,false><<<gq,256>>>(wk, xn, k, CH, NPOS, CH,
                                         CH, NPOS, NPOS, 0, sX, sX,
                                         1.f, bk, nullptr, 0);
    gemm_kernel<false,false><<<gq,256>>>(wv, xn, v, CH, NPOS, CH,
                                         CH, NPOS, NPOS, 0, sX, sX,
                                         1.f, bv, nullptr, 0);

    // 3. S = (1/16) * Q^T K : A = q[c,i] (TA), B = k[c,j]
    dim3 gs(NPOS/64, NPOS/64, BATCH);
    gemm_kernel<true,false><<<gs,256>>>(q, k, attn, NPOS, NPOS, CH,
                                        NPOS, NPOS, NPOS, sX, sX, sAt,
                                        0.0625f, nullptr, nullptr, 0);

    // 4. softmax over last dim
    softmax_kernel<<<BATCH*NPOS, 256>>>(attn);

    // 5. O = V * A^T : A = v[c,j], B = attn[i,j] (TB)
    gemm_kernel<false,true><<<gq,256>>>(v, attn, o, CH, NPOS, NPOS,
                                        NPOS, NPOS, NPOS, sX, sAt, sX,
                                        1.f, nullptr, nullptr, 0);

    // 6. out = Wp*O + bp + x (residual)
    gemm_kernel<false,false><<<gq,256>>>(wp, o, out, CH, NPOS, CH,
                                         CH, NPOS, NPOS, 0, sX, sX,
                                         1.f, bp, x, sX);
}

// round 3
// speedup vs baseline: 2.9752x; 2.9752x over previous
#include <cuda_runtime.h>
#include <math_constants.h>

#define BATCH 8
#define CH    256
#define NPOS  4096      // 64*64
#define NGRP  8
#define CPG   (CH/NGRP) // 32

// ---------------- scratch (device globals; no allocation allowed) ----------------
__device__ float g_xn [(size_t)BATCH*CH*NPOS];
__device__ float g_q  [(size_t)BATCH*CH*NPOS];
__device__ float g_k  [(size_t)BATCH*CH*NPOS];
__device__ float g_v  [(size_t)BATCH*CH*NPOS];
__device__ float g_o  [(size_t)BATCH*CH*NPOS];
__device__ float g_attn[(size_t)BATCH*NPOS*NPOS];   // 512 MB

// ---------------- GroupNorm ----------------
__global__ void groupnorm_kernel(const float* __restrict__ x,
                                 const float* __restrict__ gamma,
                                 const float* __restrict__ beta) {
    const int GSZ = CPG * NPOS;                     // 131072
    int b = blockIdx.x / NGRP;
    int g = blockIdx.x % NGRP;
    const float* px = x    + ((size_t)b*CH + (size_t)g*CPG) * NPOS;
    float*       po = g_xn + ((size_t)b*CH + (size_t)g*CPG) * NPOS;
    int tid = threadIdx.x;

    float s = 0.f, s2 = 0.f;
    for (int i = tid; i < GSZ; i += blockDim.x) {
        float t = px[i];
        s += t; s2 += t*t;
    }
    __shared__ float rs[32], rs2[32];
    #pragma unroll
    for (int o = 16; o > 0; o >>= 1) {
        s  += __shfl_xor_sync(0xffffffffu, s,  o);
        s2 += __shfl_xor_sync(0xffffffffu, s2, o);
    }
    int lane = tid & 31, wid = tid >> 5;
    if (lane == 0) { rs[wid] = s; rs2[wid] = s2; }
    __syncthreads();
    int nw = blockDim.x >> 5;
    if (wid == 0) {
        s  = (lane < nw) ? rs[lane]  : 0.f;
        s2 = (lane < nw) ? rs2[lane] : 0.f;
        #pragma unroll
        for (int o = 16; o > 0; o >>= 1) {
            s  += __shfl_xor_sync(0xffffffffu, s,  o);
            s2 += __shfl_xor_sync(0xffffffffu, s2, o);
        }
        if (lane == 0) { rs[0] = s; rs2[0] = s2; }
    }
    __syncthreads();
    float mean = rs[0] * (1.f / GSZ);
    float var  = rs2[0] * (1.f / GSZ) - mean*mean;
    float rstd = rsqrtf(var + 1e-5f);

    for (int i = tid; i < GSZ; i += blockDim.x) {
        int c = g*CPG + i / NPOS;
        po[i] = (px[i] - mean) * rstd * gamma[c] + beta[c];
    }
}

// ---------------- tf32 mma helper ----------------
__device__ __forceinline__ void mma_tf32(float c[4], const unsigned a[4], const unsigned b[2]) {
    asm volatile("mma.sync.aligned.m16n8k8.row.col.f32.tf32.tf32.f32 "
        "{%0,%1,%2,%3}, {%4,%5,%6,%7}, {%8,%9}, {%0,%1,%2,%3};"
        : "+f"(c[0]), "+f"(c[1]), "+f"(c[2]), "+f"(c[3])
        : "r"(a[0]), "r"(a[1]), "r"(a[2]), "r"(a[3]), "r"(b[0]), "r"(b[1]));
}

__device__ __forceinline__ unsigned to_tf32(float v) {
    unsigned u;
    asm("cvt.rna.tf32.f32 %0, %1;" : "=r"(u) : "f"(v));
    return u;
}

// ---------------- generic batched tf32 tensor-core GEMM ----------------
// C[m,n] = alpha * sum_k A(k,m)*B(k,n) + bias[m] (+ residual)
// TA: A stored as [K,M] (A[k*lda+m]) else [M,K] (A[m*lda+k])
// TB: B stored as [N,K] (B[n*ldb+k]) else [K,N] (B[k*ldb+n])
// 128x128 block tile, BK=16, 256 threads (8 warps, 2x4), 64x32 warp tile.
// M,N div by 128; K div by 16 (true for this problem).
template<bool TA, bool TB>
__global__ __launch_bounds__(256, 2)
void gemm_tf32_kernel(const float* __restrict__ A,
                      const float* __restrict__ B,
                      float* __restrict__ C,
                      int M, int N, int K,
                      int lda, int ldb, int ldc,
                      long long sA, long long sB, long long sC,
                      float alpha,
                      const float* __restrict__ bias,
                      const float* __restrict__ resid, long long sR)
{
    const int BM = 128, BN = 128, BK = 16, PAD = 8; // stride 136 ≡ 8 (mod 32): frag LDS conflict-free
    __shared__ unsigned As[BK][BM+PAD];
    __shared__ unsigned Bs[BK][BN+PAD];

    int bz = blockIdx.z;
    A += (size_t)bz * sA;
    B += (size_t)bz * sB;
    C += (size_t)bz * sC;
    const float* R = resid ? resid + (size_t)bz * sR : nullptr;

    int m0 = blockIdx.y * BM;
    int n0 = blockIdx.x * BN;
    int tid = threadIdx.x;
    int lane = tid & 31, warp = tid >> 5;
    int wm = (warp & 1) * 64;        // warp row offset (2 warps in m)
    int wn = (warp >> 1) * 32;       // warp col offset (4 warps in n)

    float acc[4][4][4] = {};

    for (int k0 = 0; k0 < K; k0 += BK) {
        #pragma unroll
        for (int i = tid; i < BK*BM; i += 256) {
            int kk, mm; float v;
            if (TA) { kk = i >> 7; mm = i & 127;
                      v = A[(size_t)(k0+kk)*lda + (m0+mm)]; }
            else    { mm = i >> 4; kk = i & 15;
                      v = A[(size_t)(m0+mm)*lda + (k0+kk)]; }
            As[kk][mm] = to_tf32(v);
        }
        #pragma unroll
        for (int i = tid; i < BK*BN; i += 256) {
            int kk, nn; float v;
            if (!TB) { kk = i >> 7; nn = i & 127;
                       v = B[(size_t)(k0+kk)*ldb + (n0+nn)]; }
            else     { nn = i >> 4; kk = i & 15;
                       v = B[(size_t)(n0+nn)*ldb + (k0+kk)]; }
            Bs[kk][nn] = to_tf32(v);
        }
        __syncthreads();

        #pragma unroll
        for (int ks = 0; ks < BK; ks += 8) {
            unsigned af[4][4], bf[4][2];
            int kr = ks + (lane & 3);
            int rr = wm + (lane >> 2);
            #pragma unroll
            for (int mi = 0; mi < 4; mi++) {
                af[mi][0] = As[kr    ][rr + mi*16];
                af[mi][1] = As[kr    ][rr + mi*16 + 8];
                af[mi][2] = As[kr + 4][rr + mi*16];
                af[mi][3] = As[kr + 4][rr + mi*16 + 8];
            }
            int cc = wn + (lane >> 2);
            #pragma unroll
            for (int nj = 0; nj < 4; nj++) {
                bf[nj][0] = Bs[kr    ][cc + nj*8];
                bf[nj][1] = Bs[kr + 4][cc + nj*8];
            }
            #pragma unroll
            for (int mi = 0; mi < 4; mi++)
                #pragma unroll
                for (int nj = 0; nj < 4; nj++)
                    mma_tf32(acc[mi][nj], af[mi], bf[nj]);
        }
        __syncthreads();
    }

    // epilogue: c0,c1 -> (row, 2*(lane&3)+{0,1}); c2,c3 -> row+8
    #pragma unroll
    for (int mi = 0; mi < 4; mi++) {
        #pragma unroll
        for (int half = 0; half < 2; half++) {
            int m = m0 + wm + mi*16 + (lane >> 2) + half*8;
            float bv = bias ? bias[m] : 0.f;
            #pragma unroll
            for (int nj = 0; nj < 4; nj++) {
                int n = n0 + wn + nj*8 + 2*(lane & 3);
                float2 val;
                val.x = acc[mi][nj][half*2+0] * alpha + bv;
                val.y = acc[mi][nj][half*2+1] * alpha + bv;
                if (R) {
                    val.x += R[(size_t)m*ldc + n];
                    val.y += R[(size_t)m*ldc + n + 1];
                }
                *reinterpret_cast<float2*>(&C[(size_t)m*ldc + n]) = val;
            }
        }
    }
}

// ---------------- row softmax over attn[8,4096,4096] ----------------
__global__ void softmax_kernel(float* __restrict__ attn) {
    size_t row = blockIdx.x;
    float* p = attn + row * NPOS;
    int tid  = threadIdx.x;        // 256 threads, 16 elems each
    int lane = tid & 31, wid = tid >> 5;

    float v[16];
    float mx = -CUDART_INF_F;
    #pragma unroll
    for (int i = 0; i < 16; i++) { v[i] = p[tid + 256*i]; mx = fmaxf(mx, v[i]); }

    __shared__ float red[32];
    #pragma unroll
    for (int o = 16; o > 0; o >>= 1) mx = fmaxf(mx, __shfl_xor_sync(0xffffffffu, mx, o));
    if (lane == 0) red[wid] = mx;
    __syncthreads();
    if (wid == 0) {
        float t = (lane < 8) ? red[lane] : -CUDART_INF_F;
        #pragma unroll
        for (int o = 4; o > 0; o >>= 1) t = fmaxf(t, __shfl_xor_sync(0xffffffffu, t, o));
        if (lane == 0) red[0] = t;
    }
    __syncthreads();
    mx = red[0];

    float s = 0.f;
    #pragma unroll
    for (int i = 0; i < 16; i++) { v[i] = __expf(v[i] - mx); s += v[i]; }
    __shared__ float red2[32];
    #pragma unroll
    for (int o = 16; o > 0; o >>= 1) s += __shfl_xor_sync(0xffffffffu, s, o);
    if (lane == 0) red2[wid] = s;
    __syncthreads();
    if (wid == 0) {
        float t = (lane < 8) ? red2[lane] : 0.f;
        #pragma unroll
        for (int o = 4; o > 0; o >>= 1) t += __shfl_xor_sync(0xffffffffu, t, o);
        if (lane == 0) red2[0] = t;
    }
    __syncthreads();
    float inv = 1.f / red2[0];
    #pragma unroll
    for (int i = 0; i < 16; i++) p[tid + 256*i] = v[i] * inv;
}

// ---------------- launcher ----------------
extern "C" void kernel_launch(void* const* d_in, const int* in_sizes, int n_in,
                              void* d_out, int out_size) {
    const float* x     = (const float*)d_in[0];
    const float* gamma = (const float*)d_in[1];
    const float* beta  = (const float*)d_in[2];
    const float* wq    = (const float*)d_in[3];
    const float* bq    = (const float*)d_in[4];
    const float* wk    = (const float*)d_in[5];
    const float* bk    = (const float*)d_in[6];
    const float* wv    = (const float*)d_in[7];
    const float* bv    = (const float*)d_in[8];
    const float* wp    = (const float*)d_in[9];
    const float* bp    = (const float*)d_in[10];
    float* out = (float*)d_out;

    float *xn, *q, *k, *v, *o, *attn;
    cudaGetSymbolAddress((void**)&xn,   g_xn);
    cudaGetSymbolAddress((void**)&q,    g_q);
    cudaGetSymbolAddress((void**)&k,    g_k);
    cudaGetSymbolAddress((void**)&v,    g_v);
    cudaGetSymbolAddress((void**)&o,    g_o);
    cudaGetSymbolAddress((void**)&attn, g_attn);

    // 1. GroupNorm
    groupnorm_kernel<<<BATCH*NGRP, 1024>>>(x, gamma, beta);

    const long long sX  = (long long)CH * NPOS;        // per-batch activation stride
    const long long sAt = (long long)NPOS * NPOS;      // per-batch attn stride

    // 2. Q/K/V projections: W[256,256] x Xn[256,4096]
    dim3 gq(NPOS/128, CH/128, BATCH);
    gemm_tf32_kernel<false,false><<<gq,256>>>(wq, xn, q, CH, NPOS, CH,
                                              CH, NPOS, NPOS, 0, sX, sX,
                                              1.f, bq, nullptr, 0);
    gemm_tf32_kernel<false,false><<<gq,256>>>(wk, xn, k, CH, NPOS, CH,
                                              CH, NPOS, NPOS, 0, sX, sX,
                                              1.f, bk, nullptr, 0);
    gemm_tf32_kernel<false,false><<<gq,256>>>(wv, xn, v, CH, NPOS, CH,
                                              CH, NPOS, NPOS, 0, sX, sX,
                                              1.f, bv, nullptr, 0);

    // 3. S = (1/16) * Q^T K
    dim3 gs(NPOS/128, NPOS/128, BATCH);
    gemm_tf32_kernel<true,false><<<gs,256>>>(q, k, attn, NPOS, NPOS, CH,
                                             NPOS, NPOS, NPOS, sX, sX, sAt,
                                             0.0625f, nullptr, nullptr, 0);

    // 4. softmax over last dim
    softmax_kernel<<<BATCH*NPOS, 256>>>(attn);

    // 5. O = V * A^T
    gemm_tf32_kernel<false,true><<<gq,256>>>(v, attn, o, CH, NPOS, NPOS,
                                             NPOS, NPOS, NPOS, sX, sAt, sX,
                                             1.f, nullptr, nullptr, 0);

    // 6. out = Wp*O + bp + x (residual)
    gemm_tf32_kernel<false,false><<<gq,256>>>(wp, o, out, CH, NPOS, CH,
                                              CH, NPOS, NPOS, 0, sX, sX,
                                              1.f, bp, x, sX);
}

// round 4
// speedup vs baseline: 5.3833x; 1.8094x over previous
#include <cuda_runtime.h>
#include <cuda_fp16.h>
#include <math_constants.h>

#define BATCH 8
#define CH    256
#define NPOS  4096      // 64*64
#define NGRP  8
#define CPG   (CH/NGRP) // 32

// ---------------- scratch (device globals; no allocation allowed) ----------------
__device__ __align__(16) __half h_xn [(size_t)BATCH*CH*NPOS];
__device__ __align__(16) __half h_q  [(size_t)BATCH*CH*NPOS];
__device__ __align__(16) __half h_k  [(size_t)BATCH*CH*NPOS];
__device__ __align__(16) __half h_v  [(size_t)BATCH*CH*NPOS];
__device__ __align__(16) __half h_o  [(size_t)BATCH*CH*NPOS];
__device__ __align__(16) __half h_attn[(size_t)BATCH*NPOS*NPOS];   // 256 MB
__device__ __align__(16) __half h_w  [4*(size_t)CH*CH];

// ---------------- weight fp32 -> fp16 conversion ----------------
__global__ void wcvt_kernel(const float* __restrict__ wq, const float* __restrict__ wk,
                            const float* __restrict__ wv, const float* __restrict__ wp) {
    int i = blockIdx.x * 256 + threadIdx.x;     // 65536 per weight
    h_w[i             ] = __float2half(wq[i]);
    h_w[i +   CH*CH   ] = __float2half(wk[i]);
    h_w[i + 2*CH*CH   ] = __float2half(wv[i]);
    h_w[i + 3*CH*CH   ] = __float2half(wp[i]);
}

// ---------------- GroupNorm (fp32 in, fp16 out) ----------------
__global__ void groupnorm_kernel(const float* __restrict__ x,
                                 const float* __restrict__ gamma,
                                 const float* __restrict__ beta) {
    const int GSZ = CPG * NPOS;                 // 131072
    int b = blockIdx.x / NGRP;
    int g = blockIdx.x % NGRP;
    const float* px = x    + ((size_t)b*CH + (size_t)g*CPG) * NPOS;
    __half*      po = h_xn + ((size_t)b*CH + (size_t)g*CPG) * NPOS;
    int tid = threadIdx.x;

    float s = 0.f, s2 = 0.f;
    for (int i = tid; i < GSZ; i += blockDim.x) {
        float t = px[i];
        s += t; s2 += t*t;
    }
    __shared__ float rs[32], rs2[32];
    #pragma unroll
    for (int o = 16; o > 0; o >>= 1) {
        s  += __shfl_xor_sync(0xffffffffu, s,  o);
        s2 += __shfl_xor_sync(0xffffffffu, s2, o);
    }
    int lane = tid & 31, wid = tid >> 5;
    if (lane == 0) { rs[wid] = s; rs2[wid] = s2; }
    __syncthreads();
    int nw = blockDim.x >> 5;
    if (wid == 0) {
        s  = (lane < nw) ? rs[lane]  : 0.f;
        s2 = (lane < nw) ? rs2[lane] : 0.f;
        #pragma unroll
        for (int o = 16; o > 0; o >>= 1) {
            s  += __shfl_xor_sync(0xffffffffu, s,  o);
            s2 += __shfl_xor_sync(0xffffffffu, s2, o);
        }
        if (lane == 0) { rs[0] = s; rs2[0] = s2; }
    }
    __syncthreads();
    float mean = rs[0] * (1.f / GSZ);
    float var  = rs2[0] * (1.f / GSZ) - mean*mean;
    float rstd = rsqrtf(var + 1e-5f);

    for (int i = tid; i < GSZ; i += blockDim.x) {
        int c = g*CPG + i / NPOS;
        po[i] = __float2half((px[i] - mean) * rstd * gamma[c] + beta[c]);
    }
}

// ---------------- mma / ldmatrix helpers ----------------
__device__ __forceinline__ void mma_f16(float c[4], const unsigned a[4], const unsigned b[2]) {
    asm volatile("mma.sync.aligned.m16n8k16.row.col.f32.f16.f16.f32 "
        "{%0,%1,%2,%3}, {%4,%5,%6,%7}, {%8,%9}, {%0,%1,%2,%3};"
        : "+f"(c[0]), "+f"(c[1]), "+f"(c[2]), "+f"(c[3])
        : "r"(a[0]), "r"(a[1]), "r"(a[2]), "r"(a[3]), "r"(b[0]), "r"(b[1]));
}
__device__ __forceinline__ void ldsm4(unsigned &r0, unsigned &r1, unsigned &r2, unsigned &r3, unsigned addr) {
    asm volatile("ldmatrix.sync.aligned.m8n8.x4.shared.b16 {%0,%1,%2,%3}, [%4];"
        : "=r"(r0), "=r"(r1), "=r"(r2), "=r"(r3) : "r"(addr));
}
__device__ __forceinline__ void ldsm4t(unsigned &r0, unsigned &r1, unsigned &r2, unsigned &r3, unsigned addr) {
    asm volatile("ldmatrix.sync.aligned.m8n8.x4.trans.shared.b16 {%0,%1,%2,%3}, [%4];"
        : "=r"(r0), "=r"(r1), "=r"(r2), "=r"(r3) : "r"(addr));
}

// ---------------- generic batched fp16 tensor-core GEMM ----------------
// C[m,n] = alpha * sum_k A(k,m)*B(k,n) + bias[m] (+ residual)
// AKM: A gmem stored [K][M] (k-major)  else [M][K]
// BNM: B gmem stored [N][K] (n-major)  else [K][N]
// 128x128x32 tile, 256 threads (8 warps 2x4), 64x32 warp tile, double-buffered.
template<bool AKM, bool BNM, bool OUTF32>
__global__ __launch_bounds__(256, 1)
void hgemm_kernel(const __half* __restrict__ A, const __half* __restrict__ B,
                  void* __restrict__ Cp,
                  int K, int lda, int ldb, int ldc,
                  long long sA, long long sB, long long sC,
                  float alpha,
                  const float* __restrict__ bias,
                  const float* __restrict__ resid, long long sR)
{
    const int BM = 128, BN = 128;
    constexpr int ASZ = AKM ? 32*136 : 128*40;
    constexpr int BSZ = BNM ? 128*40 : 32*136;
    __shared__ __align__(16) __half As[2][ASZ];
    __shared__ __align__(16) __half Bs[2][BSZ];

    int bz = blockIdx.z;
    A += (size_t)bz * sA;
    B += (size_t)bz * sB;
    int m0 = blockIdx.y * BM;
    int n0 = blockIdx.x * BN;
    int tid = threadIdx.x, lane = tid & 31, warp = tid >> 5;
    int wm = (warp & 1) * 64;
    int wn = (warp >> 1) * 32;

    // global load setup: 2 uint4 per thread per operand per stage
    const __half* aptr[2]; int asmo[2];
    const __half* bptr[2]; int bsmo[2];
    #pragma unroll
    for (int i = 0; i < 2; i++) {
        int idx = tid + i*256;
        if (AKM) { int r = idx >> 4, c = (idx & 15)*8;
                   aptr[i] = A + (size_t)r*lda + m0 + c; asmo[i] = r*136 + c; }
        else     { int r = idx >> 2, c = (idx & 3)*8;
                   aptr[i] = A + (size_t)(m0+r)*lda + c; asmo[i] = r*40 + c; }
        if (BNM) { int r = idx >> 2, c = (idx & 3)*8;
                   bptr[i] = B + (size_t)(n0+r)*ldb + c; bsmo[i] = r*40 + c; }
        else     { int r = idx >> 4, c = (idx & 15)*8;
                   bptr[i] = B + (size_t)r*ldb + n0 + c; bsmo[i] = r*136 + c; }
    }
    const long long stepA = AKM ? (long long)32*lda : 32;
    const long long stepB = BNM ? 32 : (long long)32*ldb;

    float acc[4][4][4] = {};

    // prologue: stage 0
    uint4 ra[2], rb[2];
    #pragma unroll
    for (int i = 0; i < 2; i++) {
        ra[i] = *(const uint4*)aptr[i];
        rb[i] = *(const uint4*)bptr[i];
        aptr[i] += stepA; bptr[i] += stepB;
    }
    #pragma unroll
    for (int i = 0; i < 2; i++) {
        *(uint4*)&As[0][asmo[i]] = ra[i];
        *(uint4*)&Bs[0][bsmo[i]] = rb[i];
    }
    __syncthreads();

    int nstage = K >> 5;
    for (int s = 0; s < nstage; s++) {
        int cur = s & 1;
        bool more = (s + 1 < nstage);
        if (more) {
            #pragma unroll
            for (int i = 0; i < 2; i++) {
                ra[i] = *(const uint4*)aptr[i];
                rb[i] = *(const uint4*)bptr[i];
                aptr[i] += stepA; bptr[i] += stepB;
            }
        }

        unsigned abase = (unsigned)__cvta_generic_to_shared(&As[cur][0]);
        unsigned bbase = (unsigned)__cvta_generic_to_shared(&Bs[cur][0]);
        #pragma unroll
        for (int ks = 0; ks < 2; ks++) {
            unsigned af[4][4], bf[4][2];
            #pragma unroll
            for (int mi = 0; mi < 4; mi++) {
                unsigned addr;
                if (AKM) {
                    addr = abase + 2u*(((lane&7) + ((lane>>4)&1)*8 + ks*16)*136
                                        + wm + mi*16 + ((lane>>3)&1)*8);
                    ldsm4t(af[mi][0], af[mi][1], af[mi][2], af[mi][3], addr);
                } else {
                    addr = abase + 2u*((wm + mi*16 + (lane&15))*40 + ks*16 + (lane>>4)*8);
                    ldsm4(af[mi][0], af[mi][1], af[mi][2], af[mi][3], addr);
                }
            }
            #pragma unroll
            for (int bi = 0; bi < 2; bi++) {
                unsigned q0, q1, q2, q3, addr;
                if (BNM) {
                    addr = bbase + 2u*((wn + bi*16 + (lane&7) + (lane>>4)*8)*40
                                        + ks*16 + ((lane>>3)&1)*8);
                    ldsm4(q0, q1, q2, q3, addr);
                } else {
                    addr = bbase + 2u*(((lane&7) + ((lane>>3)&1)*8 + ks*16)*136
                                        + wn + bi*16 + (lane>>4)*8);
                    ldsm4t(q0, q1, q2, q3, addr);
                }
                bf[bi*2  ][0] = q0; bf[bi*2  ][1] = q1;
                bf[bi*2+1][0] = q2; bf[bi*2+1][1] = q3;
            }
            #pragma unroll
            for (int mi = 0; mi < 4; mi++)
                #pragma unroll
                for (int nj = 0; nj < 4; nj++)
                    mma_f16(acc[mi][nj], af[mi], bf[nj]);
        }

        if (more) {
            int nxt = cur ^ 1;
            #pragma unroll
            for (int i = 0; i < 2; i++) {
                *(uint4*)&As[nxt][asmo[i]] = ra[i];
                *(uint4*)&Bs[nxt][bsmo[i]] = rb[i];
            }
            __syncthreads();
        }
    }

    // epilogue
    if (OUTF32) {
        float* C = (float*)Cp + (size_t)bz * sC;
        const float* R = resid ? resid + (size_t)bz * sR : nullptr;
        #pragma unroll
        for (int mi = 0; mi < 4; mi++) {
            #pragma unroll
            for (int h = 0; h < 2; h++) {
                int m = m0 + wm + mi*16 + (lane >> 2) + h*8;
                float bv = bias ? bias[m] : 0.f;
                #pragma unroll
                for (int nj = 0; nj < 4; nj++) {
                    int n = n0 + wn + nj*8 + 2*(lane & 3);
                    float2 val;
                    val.x = acc[mi][nj][h*2+0] * alpha + bv;
                    val.y = acc[mi][nj][h*2+1] * alpha + bv;
                    if (R) {
                        val.x += R[(size_t)m*ldc + n];
                        val.y += R[(size_t)m*ldc + n + 1];
                    }
                    *reinterpret_cast<float2*>(&C[(size_t)m*ldc + n]) = val;
                }
            }
        }
    } else {
        __half* C = (__half*)Cp + (size_t)bz * sC;
        #pragma unroll
        for (int mi = 0; mi < 4; mi++) {
            #pragma unroll
            for (int h = 0; h < 2; h++) {
                int m = m0 + wm + mi*16 + (lane >> 2) + h*8;
                float bv = bias ? bias[m] : 0.f;
                #pragma unroll
                for (int nj = 0; nj < 4; nj++) {
                    int n = n0 + wn + nj*8 + 2*(lane & 3);
                    __half2 hv = __floats2half2_rn(acc[mi][nj][h*2+0]*alpha + bv,
                                                   acc[mi][nj][h*2+1]*alpha + bv);
                    *reinterpret_cast<__half2*>(&C[(size_t)m*ldc + n]) = hv;
                }
            }
        }
    }
}

// ---------------- row softmax over h_attn[8,4096,4096] (fp16 in/out) ----------------
__global__ void softmax_kernel(__half* __restrict__ attn) {
    size_t row = blockIdx.x;
    __half* p = attn + row * NPOS;
    uint4* pv = reinterpret_cast<uint4*>(p);
    int tid  = threadIdx.x;        // 256 threads, 16 halves each (2 x uint4)
    int lane = tid & 31, wid = tid >> 5;

    uint4 u[2];
    u[0] = pv[tid];
    u[1] = pv[tid + 256];
    float v[16];
    #pragma unroll
    for (int i = 0; i < 2; i++) {
        const __half2* h2 = reinterpret_cast<const __half2*>(&u[i]);
        #pragma unroll
        for (int j = 0; j < 4; j++) {
            float2 f = __half22float2(h2[j]);
            v[i*8 + j*2 + 0] = f.x;
            v[i*8 + j*2 + 1] = f.y;
        }
    }

    float mx = -CUDART_INF_F;
    #pragma unroll
    for (int i = 0; i < 16; i++) mx = fmaxf(mx, v[i]);

    __shared__ float red[32];
    #pragma unroll
    for (int o = 16; o > 0; o >>= 1) mx = fmaxf(mx, __shfl_xor_sync(0xffffffffu, mx, o));
    if (lane == 0) red[wid] = mx;
    __syncthreads();
    if (wid == 0) {
        float t = (lane < 8) ? red[lane] : -CUDART_INF_F;
        #pragma unroll
        for (int o = 4; o > 0; o >>= 1) t = fmaxf(t, __shfl_xor_sync(0xffffffffu, t, o));
        if (lane == 0) red[0] = t;
    }
    __syncthreads();
    mx = red[0];

    float s = 0.f;
    #pragma unroll
    for (int i = 0; i < 16; i++) { v[i] = __expf(v[i] - mx); s += v[i]; }
    __shared__ float red2[32];
    #pragma unroll
    for (int o = 16; o > 0; o >>= 1) s += __shfl_xor_sync(0xffffffffu, s, o);
    if (lane == 0) red2[wid] = s;
    __syncthreads();
    if (wid == 0) {
        float t = (lane < 8) ? red2[lane] : 0.f;
        #pragma unroll
        for (int o = 4; o > 0; o >>= 1) t += __shfl_xor_sync(0xffffffffu, t, o);
        if (lane == 0) red2[0] = t;
    }
    __syncthreads();
    float inv = 1.f / red2[0];

    #pragma unroll
    for (int i = 0; i < 2; i++) {
        __half2* h2 = reinterpret_cast<__half2*>(&u[i]);
        #pragma unroll
        for (int j = 0; j < 4; j++)
            h2[j] = __floats2half2_rn(v[i*8+j*2+0]*inv, v[i*8+j*2+1]*inv);
    }
    pv[tid]       = u[0];
    pv[tid + 256] = u[1];
}

// ---------------- launcher ----------------
extern "C" void kernel_launch(void* const* d_in, const int* in_sizes, int n_in,
                              void* d_out, int out_size) {
    const float* x     = (const float*)d_in[0];
    const float* gamma = (const float*)d_in[1];
    const float* beta  = (const float*)d_in[2];
    const float* wq    = (const float*)d_in[3];
    const float* bq    = (const float*)d_in[4];
    const float* wk    = (const float*)d_in[5];
    const float* bk    = (const float*)d_in[6];
    const float* wv    = (const float*)d_in[7];
    const float* bv    = (const float*)d_in[8];
    const float* wp    = (const float*)d_in[9];
    const float* bp    = (const float*)d_in[10];
    float* out = (float*)d_out;

    __half *xn, *q, *k, *v, *o, *attn, *w;
    cudaGetSymbolAddress((void**)&xn,   h_xn);
    cudaGetSymbolAddress((void**)&q,    h_q);
    cudaGetSymbolAddress((void**)&k,    h_k);
    cudaGetSymbolAddress((void**)&v,    h_v);
    cudaGetSymbolAddress((void**)&o,    h_o);
    cudaGetSymbolAddress((void**)&attn, h_attn);
    cudaGetSymbolAddress((void**)&w,    h_w);

    // 0. weights fp32 -> fp16
    wcvt_kernel<<<CH*CH/256, 256>>>(wq, wk, wv, wp);

    // 1. GroupNorm -> fp16 xn
    groupnorm_kernel<<<BATCH*NGRP, 1024>>>(x, gamma, beta);

    const long long sX  = (long long)CH * NPOS;
    const long long sAt = (long long)NPOS * NPOS;

    // 2. Q/K/V projections: W[256,256] x Xn[256,4096] -> fp16
    dim3 gq(NPOS/128, CH/128, BATCH);
    hgemm_kernel<false,false,false><<<gq,256>>>(w,           xn, q, CH, CH, NPOS, NPOS,
                                                0, sX, sX, 1.f, bq, nullptr, 0);
    hgemm_kernel<false,false,false><<<gq,256>>>(w +   CH*CH, xn, k, CH, CH, NPOS, NPOS,
                                                0, sX, sX, 1.f, bk, nullptr, 0);
    hgemm_kernel<false,false,false><<<gq,256>>>(w + 2*CH*CH, xn, v, CH, CH, NPOS, NPOS,
                                                0, sX, sX, 1.f, bv, nullptr, 0);

    // 3. S = (1/16) * Q^T K  (A = q [c][i] k-major, B = k [c][j])
    dim3 gs(NPOS/128, NPOS/128, BATCH);
    hgemm_kernel<true,false,false><<<gs,256>>>(q, k, attn, CH, NPOS, NPOS, NPOS,
                                               sX, sX, sAt, 0.0625f, nullptr, nullptr, 0);

    // 4. softmax over last dim
    softmax_kernel<<<BATCH*NPOS, 256>>>(attn);

    // 5. O = V * A^T  (A = v [c][j], B = attn [i][j] n-major)
    hgemm_kernel<false,true,false><<<gq,256>>>(v, attn, o, NPOS, NPOS, NPOS, NPOS,
                                               sX, sAt, sX, 1.f, nullptr, nullptr, 0);

    // 6. out = Wp*O + bp + x (residual, fp32 out)
    hgemm_kernel<false,false,true><<<gq,256>>>(w + 3*CH*CH, o, out, CH, CH, NPOS, NPOS,
                                               0, sX, sX, 1.f, bp, x, sX);
}

// round 6
// speedup vs baseline: 7.2204x; 1.3413x over previous
#include <cuda_runtime.h>
#include <cuda_fp16.h>
#include <math_constants.h>

#define BATCH 8
#define CH    256
#define NPOS  4096      // 64*64
#define NGRP  8
#define CPG   (CH/NGRP) // 32

// ---------------- scratch (device globals; no allocation allowed) ----------------
__device__ __align__(16) __half h_xn [(size_t)BATCH*CH*NPOS];
__device__ __align__(16) __half h_q  [(size_t)BATCH*CH*NPOS];
__device__ __align__(16) __half h_k  [(size_t)BATCH*CH*NPOS];
__device__ __align__(16) __half h_v  [(size_t)BATCH*CH*NPOS];
__device__ __align__(16) __half h_o  [(size_t)BATCH*CH*NPOS];
__device__ __align__(16) __half h_attn[(size_t)BATCH*NPOS*NPOS];   // 256 MB
__device__ __align__(16) __half h_w  [4*(size_t)CH*CH];

// ---------------- cp.async helpers ----------------
__device__ __forceinline__ void cp_async16(unsigned dst, const void* src) {
    asm volatile("cp.async.cg.shared.global [%0], [%1], 16;" :: "r"(dst), "l"(src));
}
__device__ __forceinline__ void cp_commit() {
    asm volatile("cp.async.commit_group;");
}
template<int N>
__device__ __forceinline__ void cp_wait() {
    asm volatile("cp.async.wait_group %0;" :: "n"(N));
}

// ---------------- weight fp32 -> fp16 conversion ----------------
__global__ void wcvt_kernel(const float* __restrict__ wq, const float* __restrict__ wk,
                            const float* __restrict__ wv, const float* __restrict__ wp) {
    int i = blockIdx.x * 256 + threadIdx.x;     // 65536 per weight
    h_w[i          ] = __float2half(wq[i]);
    h_w[i +   CH*CH] = __float2half(wk[i]);
    h_w[i + 2*CH*CH] = __float2half(wv[i]);
    h_w[i + 3*CH*CH] = __float2half(wp[i]);
}

// ---------------- GroupNorm (fp32 in, fp16 out) ----------------
__global__ void groupnorm_kernel(const float* __restrict__ x,
                                 const float* __restrict__ gamma,
                                 const float* __restrict__ beta) {
    const int GSZ = CPG * NPOS;                 // 131072
    int b = blockIdx.x / NGRP;
    int g = blockIdx.x % NGRP;
    const float* px = x    + ((size_t)b*CH + (size_t)g*CPG) * NPOS;
    __half*      po = h_xn + ((size_t)b*CH + (size_t)g*CPG) * NPOS;
    int tid = threadIdx.x;

    float s = 0.f, s2 = 0.f;
    for (int i = tid; i < GSZ; i += blockDim.x) {
        float t = px[i];
        s += t; s2 += t*t;
    }
    __shared__ float rs[32], rs2[32];
    #pragma unroll
    for (int o = 16; o > 0; o >>= 1) {
        s  += __shfl_xor_sync(0xffffffffu, s,  o);
        s2 += __shfl_xor_sync(0xffffffffu, s2, o);
    }
    int lane = tid & 31, wid = tid >> 5;
    if (lane == 0) { rs[wid] = s; rs2[wid] = s2; }
    __syncthreads();
    int nw = blockDim.x >> 5;
    if (wid == 0) {
        s  = (lane < nw) ? rs[lane]  : 0.f;
        s2 = (lane < nw) ? rs2[lane] : 0.f;
        #pragma unroll
        for (int o = 16; o > 0; o >>= 1) {
            s  += __shfl_xor_sync(0xffffffffu, s,  o);
            s2 += __shfl_xor_sync(0xffffffffu, s2, o);
        }
        if (lane == 0) { rs[0] = s; rs2[0] = s2; }
    }
    __syncthreads();
    float mean = rs[0] * (1.f / GSZ);
    float var  = rs2[0] * (1.f / GSZ) - mean*mean;
    float rstd = rsqrtf(var + 1e-5f);

    for (int i = tid; i < GSZ; i += blockDim.x) {
        int c = g*CPG + i / NPOS;
        po[i] = __float2half((px[i] - mean) * rstd * gamma[c] + beta[c]);
    }
}

// ---------------- mma / ldmatrix helpers ----------------
__device__ __forceinline__ void mma_f16(float c[4], const unsigned a[4], const unsigned b[2]) {
    asm volatile("mma.sync.aligned.m16n8k16.row.col.f32.f16.f16.f32 "
        "{%0,%1,%2,%3}, {%4,%5,%6,%7}, {%8,%9}, {%0,%1,%2,%3};"
        : "+f"(c[0]), "+f"(c[1]), "+f"(c[2]), "+f"(c[3])
        : "r"(a[0]), "r"(a[1]), "r"(a[2]), "r"(a[3]), "r"(b[0]), "r"(b[1]));
}
__device__ __forceinline__ void ldsm4(unsigned &r0, unsigned &r1, unsigned &r2, unsigned &r3, unsigned addr) {
    asm volatile("ldmatrix.sync.aligned.m8n8.x4.shared.b16 {%0,%1,%2,%3}, [%4];"
        : "=r"(r0), "=r"(r1), "=r"(r2), "=r"(r3) : "r"(addr));
}
__device__ __forceinline__ void ldsm4t(unsigned &r0, unsigned &r1, unsigned &r2, unsigned &r3, unsigned addr) {
    asm volatile("ldmatrix.sync.aligned.m8n8.x4.trans.shared.b16 {%0,%1,%2,%3}, [%4];"
        : "=r"(r0), "=r"(r1), "=r"(r2), "=r"(r3) : "r"(addr));
}

// ---------------- generic batched fp16 tensor-core GEMM ----------------
// C[m,n] = alpha * sum_k A(k,m)*B(k,n) + bias[m] (+ residual)
// AKM: A gmem stored [K][M] (k-major)  else [M][K]
// BNM: B gmem stored [N][K] (n-major)  else [K][N]
// 128x128x32 tile, 256 threads (8 warps 2x4), 64x32 warp tile,
// 3-stage cp.async pipeline.
template<bool AKM, bool BNM, bool OUTF32>
__global__ __launch_bounds__(256, 1)
void hgemm_kernel(const __half* __restrict__ A, const __half* __restrict__ B,
                  void* __restrict__ Cp,
                  int K, int lda, int ldb, int ldc,
                  long long sA, long long sB, long long sC,
                  float alpha,
                  const float* __restrict__ bias,
                  const float* __restrict__ resid, long long sR)
{
    const int BM = 128, BN = 128;
    constexpr int ASZ = AKM ? 32*136 : 128*40;
    constexpr int BSZ = BNM ? 128*40 : 32*136;
    __shared__ __align__(16) __half As[3][ASZ];
    __shared__ __align__(16) __half Bs[3][BSZ];

    int bz = blockIdx.z;
    A += (size_t)bz * sA;
    B += (size_t)bz * sB;
    int m0 = blockIdx.y * BM;
    int n0 = blockIdx.x * BN;
    int tid = threadIdx.x, lane = tid & 31, warp = tid >> 5;
    int wm = (warp & 1) * 64;
    int wn = (warp >> 1) * 32;

    // global load setup: 2 x 16B per thread per operand per stage
    const __half* aptr[2]; int asmo[2];
    const __half* bptr[2]; int bsmo[2];
    #pragma unroll
    for (int i = 0; i < 2; i++) {
        int idx = tid + i*256;
        if (AKM) { int r = idx >> 4, c = (idx & 15)*8;
                   aptr[i] = A + (size_t)r*lda + m0 + c; asmo[i] = r*136 + c; }
        else     { int r = idx >> 2, c = (idx & 3)*8;
                   aptr[i] = A + (size_t)(m0+r)*lda + c; asmo[i] = r*40 + c; }
        if (BNM) { int r = idx >> 2, c = (idx & 3)*8;
                   bptr[i] = B + (size_t)(n0+r)*ldb + c; bsmo[i] = r*40 + c; }
        else     { int r = idx >> 4, c = (idx & 15)*8;
                   bptr[i] = B + (size_t)r*ldb + n0 + c; bsmo[i] = r*136 + c; }
    }
    const long long stepA = AKM ? (long long)32*lda : 32;
    const long long stepB = BNM ? 32 : (long long)32*ldb;

    unsigned abase = (unsigned)__cvta_generic_to_shared(&As[0][0]);
    unsigned bbase = (unsigned)__cvta_generic_to_shared(&Bs[0][0]);

    // prologue: issue stages 0 and 1
    #pragma unroll
    for (int st = 0; st < 2; st++) {
        #pragma unroll
        for (int i = 0; i < 2; i++) {
            cp_async16(abase + (st*ASZ + asmo[i])*2u, aptr[i]);
            cp_async16(bbase + (st*BSZ + bsmo[i])*2u, bptr[i]);
            aptr[i] += stepA; bptr[i] += stepB;
        }
        cp_commit();
    }

    float acc[4][4][4] = {};
    int nk = K >> 5;

    for (int s = 0; s < nk; s++) {
        cp_wait<1>();
        __syncthreads();

        // issue stage s+2 into buffer (s+2)%3 (freed by sync above)
        if (s + 2 < nk) {
            int st = (s + 2) % 3;
            #pragma unroll
            for (int i = 0; i < 2; i++) {
                cp_async16(abase + (st*ASZ + asmo[i])*2u, aptr[i]);
                cp_async16(bbase + (st*BSZ + bsmo[i])*2u, bptr[i]);
                aptr[i] += stepA; bptr[i] += stepB;
            }
        }
        cp_commit();   // one group per iteration (empty in tail) keeps wait<1> valid

        int cur = s % 3;
        unsigned ab = abase + (unsigned)(cur*ASZ)*2u;
        unsigned bb = bbase + (unsigned)(cur*BSZ)*2u;

        unsigned af[2][4][4], bf[2][4][2];
        #pragma unroll
        for (int ks = 0; ks < 2; ks++) {
            #pragma unroll
            for (int mi = 0; mi < 4; mi++) {
                unsigned addr;
                if (AKM) {
                    addr = ab + 2u*(((lane&7) + ((lane>>4)&1)*8 + ks*16)*136
                                     + wm + mi*16 + ((lane>>3)&1)*8);
                    ldsm4t(af[ks][mi][0], af[ks][mi][1], af[ks][mi][2], af[ks][mi][3], addr);
                } else {
                    addr = ab + 2u*((wm + mi*16 + (lane&15))*40 + ks*16 + (lane>>4)*8);
                    ldsm4(af[ks][mi][0], af[ks][mi][1], af[ks][mi][2], af[ks][mi][3], addr);
                }
            }
            #pragma unroll
            for (int bi = 0; bi < 2; bi++) {
                unsigned q0, q1, q2, q3, addr;
                if (BNM) {
                    addr = bb + 2u*((wn + bi*16 + (lane&7) + (lane>>4)*8)*40
                                     + ks*16 + ((lane>>3)&1)*8);
                    ldsm4(q0, q1, q2, q3, addr);
                } else {
                    addr = bb + 2u*(((lane&7) + ((lane>>3)&1)*8 + ks*16)*136
                                     + wn + bi*16 + (lane>>4)*8);
                    ldsm4t(q0, q1, q2, q3, addr);
                }
                bf[ks][bi*2  ][0] = q0; bf[ks][bi*2  ][1] = q1;
                bf[ks][bi*2+1][0] = q2; bf[ks][bi*2+1][1] = q3;
            }
        }
        #pragma unroll
        for (int ks = 0; ks < 2; ks++)
            #pragma unroll
            for (int mi = 0; mi < 4; mi++)
                #pragma unroll
                for (int nj = 0; nj < 4; nj++)
                    mma_f16(acc[mi][nj], af[ks][mi], bf[ks][nj]);
    }

    // epilogue
    if (OUTF32) {
        float* C = (float*)Cp + (size_t)bz * sC;
        const float* R = resid ? resid + (size_t)bz * sR : nullptr;
        #pragma unroll
        for (int mi = 0; mi < 4; mi++) {
            #pragma unroll
            for (int h = 0; h < 2; h++) {
                int m = m0 + wm + mi*16 + (lane >> 2) + h*8;
                float bv = bias ? bias[m] : 0.f;
                #pragma unroll
                for (int nj = 0; nj < 4; nj++) {
                    int n = n0 + wn + nj*8 + 2*(lane & 3);
                    float2 val;
                    val.x = acc[mi][nj][h*2+0] * alpha + bv;
                    val.y = acc[mi][nj][h*2+1] * alpha + bv;
                    if (R) {
                        val.x += R[(size_t)m*ldc + n];
                        val.y += R[(size_t)m*ldc + n + 1];
                    }
                    *reinterpret_cast<float2*>(&C[(size_t)m*ldc + n]) = val;
                }
            }
        }
    } else {
        __half* C = (__half*)Cp + (size_t)bz * sC;
        #pragma unroll
        for (int mi = 0; mi < 4; mi++) {
            #pragma unroll
            for (int h = 0; h < 2; h++) {
                int m = m0 + wm + mi*16 + (lane >> 2) + h*8;
                float bv = bias ? bias[m] : 0.f;
                #pragma unroll
                for (int nj = 0; nj < 4; nj++) {
                    int n = n0 + wn + nj*8 + 2*(lane & 3);
                    __half2 hv = __floats2half2_rn(acc[mi][nj][h*2+0]*alpha + bv,
                                                   acc[mi][nj][h*2+1]*alpha + bv);
                    *reinterpret_cast<__half2*>(&C[(size_t)m*ldc + n]) = hv;
                }
            }
        }
    }
}

// ---------------- row softmax over h_attn[8,4096,4096] (fp16 in/out) ----------------
__global__ void softmax_kernel(__half* __restrict__ attn) {
    size_t row = blockIdx.x;
    __half* p = attn + row * NPOS;
    uint4* pv = reinterpret_cast<uint4*>(p);
    int tid  = threadIdx.x;        // 256 threads, 16 halves each (2 x uint4)
    int lane = tid & 31, wid = tid >> 5;

    uint4 u[2];
    u[0] = pv[tid];
    u[1] = pv[tid + 256];
    float v[16];
    #pragma unroll
    for (int i = 0; i < 2; i++) {
        const __half2* h2 = reinterpret_cast<const __half2*>(&u[i]);
        #pragma unroll
        for (int j = 0; j < 4; j++) {
            float2 f = __half22float2(h2[j]);
            v[i*8 + j*2 + 0] = f.x;
            v[i*8 + j*2 + 1] = f.y;
        }
    }

    float mx = -CUDART_INF_F;
    #pragma unroll
    for (int i = 0; i < 16; i++) mx = fmaxf(mx, v[i]);

    __shared__ float red[32];
    #pragma unroll
    for (int o = 16; o > 0; o >>= 1) mx = fmaxf(mx, __shfl_xor_sync(0xffffffffu, mx, o));
    if (lane == 0) red[wid] = mx;
    __syncthreads();
    if (wid == 0) {
        float t = (lane < 8) ? red[lane] : -CUDART_INF_F;
        #pragma unroll
        for (int o = 4; o > 0; o >>= 1) t = fmaxf(t, __shfl_xor_sync(0xffffffffu, t, o));
        if (lane == 0) red[0] = t;
    }
    __syncthreads();
    mx = red[0];

    float s = 0.f;
    #pragma unroll
    for (int i = 0; i < 16; i++) { v[i] = __expf(v[i] - mx); s += v[i]; }
    __shared__ float red2[32];
    #pragma unroll
    for (int o = 16; o > 0; o >>= 1) s += __shfl_xor_sync(0xffffffffu, s, o);
    if (lane == 0) red2[wid] = s;
    __syncthreads();
    if (wid == 0) {
        float t = (lane < 8) ? red2[lane] : 0.f;
        #pragma unroll
        for (int o = 4; o > 0; o >>= 1) t += __shfl_xor_sync(0xffffffffu, t, o);
        if (lane == 0) red2[0] = t;
    }
    __syncthreads();
    float inv = 1.f / red2[0];

    #pragma unroll
    for (int i = 0; i < 2; i++) {
        __half2* h2 = reinterpret_cast<__half2*>(&u[i]);
        #pragma unroll
        for (int j = 0; j < 4; j++)
            h2[j] = __floats2half2_rn(v[i*8+j*2+0]*inv, v[i*8+j*2+1]*inv);
    }
    pv[tid]       = u[0];
    pv[tid + 256] = u[1];
}

// ---------------- launcher ----------------
extern "C" void kernel_launch(void* const* d_in, const int* in_sizes, int n_in,
                              void* d_out, int out_size) {
    const float* x     = (const float*)d_in[0];
    const float* gamma = (const float*)d_in[1];
    const float* beta  = (const float*)d_in[2];
    const float* wq    = (const float*)d_in[3];
    const float* bq    = (const float*)d_in[4];
    const float* wk    = (const float*)d_in[5];
    const float* bk    = (const float*)d_in[6];
    const float* wv    = (const float*)d_in[7];
    const float* bv    = (const float*)d_in[8];
    const float* wp    = (const float*)d_in[9];
    const float* bp    = (const float*)d_in[10];
    float* out = (float*)d_out;

    __half *xn, *q, *k, *v, *o, *attn, *w;
    cudaGetSymbolAddress((void**)&xn,   h_xn);
    cudaGetSymbolAddress((void**)&q,    h_q);
    cudaGetSymbolAddress((void**)&k,    h_k);
    cudaGetSymbolAddress((void**)&v,    h_v);
    cudaGetSymbolAddress((void**)&o,    h_o);
    cudaGetSymbolAddress((void**)&attn, h_attn);
    cudaGetSymbolAddress((void**)&w,    h_w);

    // 0. weights fp32 -> fp16
    wcvt_kernel<<<CH*CH/256, 256>>>(wq, wk, wv, wp);

    // 1. GroupNorm -> fp16 xn
    groupnorm_kernel<<<BATCH*NGRP, 1024>>>(x, gamma, beta);

    const long long sX  = (long long)CH * NPOS;
    const long long sAt = (long long)NPOS * NPOS;

    // 2. Q/K/V projections: W[256,256] x Xn[256,4096] -> fp16
    dim3 gq(NPOS/128, CH/128, BATCH);
    hgemm_kernel<false,false,false><<<gq,256>>>(w,           xn, q, CH, CH, NPOS, NPOS,
                                                0, sX, sX, 1.f, bq, nullptr, 0);
    hgemm_kernel<false,false,false><<<gq,256>>>(w +   CH*CH, xn, k, CH, CH, NPOS, NPOS,
                                                0, sX, sX, 1.f, bk, nullptr, 0);
    hgemm_kernel<false,false,false><<<gq,256>>>(w + 2*CH*CH, xn, v, CH, CH, NPOS, NPOS,
                                                0, sX, sX, 1.f, bv, nullptr, 0);

    // 3. S = (1/16) * Q^T K  (A = q [c][i] k-major, B = k [c][j])
    dim3 gs(NPOS/128, NPOS/128, BATCH);
    hgemm_kernel<true,false,false><<<gs,256>>>(q, k, attn, CH, NPOS, NPOS, NPOS,
                                               sX, sX, sAt, 0.0625f, nullptr, nullptr, 0);

    // 4. softmax over last dim
    softmax_kernel<<<BATCH*NPOS, 256>>>(attn);

    // 5. O = V * A^T  (A = v [c][j], B = attn [i][j] n-major)
    hgemm_kernel<false,true,false><<<gq,256>>>(v, attn, o, NPOS, NPOS, NPOS, NPOS,
                                               sX, sAt, sX, 1.f, nullptr, nullptr, 0);

    // 6. out = Wp*O + bp + x (residual, fp32 out)
    hgemm_kernel<false,false,true><<<gq,256>>>(w + 3*CH*CH, o, out, CH, CH, NPOS, NPOS,
                                               0, sX, sX, 1.f, bp, x, sX);
}

// round 8
// speedup vs baseline: 9.4067x; 1.3028x over previous
#include <cuda_runtime.h>
#include <cuda_fp16.h>
#include <math_constants.h>

#define BATCH 8
#define CH    256
#define NPOS  4096      // 64*64
#define NGRP  8
#define CPG   (CH/NGRP) // 32
#define GSPLIT 8

// ---------------- scratch (device globals; no allocation allowed) ----------------
__device__ __align__(16) __half h_xn [(size_t)BATCH*CH*NPOS];
__device__ __align__(16) __half h_q  [(size_t)BATCH*CH*NPOS];
__device__ __align__(16) __half h_k  [(size_t)BATCH*CH*NPOS];
__device__ __align__(16) __half h_v  [(size_t)BATCH*CH*NPOS];
__device__ __align__(16) __half h_o  [(size_t)BATCH*CH*NPOS];
__device__ __align__(16) __half h_attn[(size_t)BATCH*NPOS*NPOS];   // 256 MB
__device__ __align__(16) __half h_w  [4*(size_t)CH*CH];
__device__ float g_part [BATCH*NGRP*GSPLIT*2];
__device__ float g_stats[BATCH*NGRP*2];

// ---------------- cp.async helpers ----------------
__device__ __forceinline__ void cp_async16(unsigned dst, const void* src) {
    asm volatile("cp.async.cg.shared.global [%0], [%1], 16;" :: "r"(dst), "l"(src));
}
__device__ __forceinline__ void cp_commit() {
    asm volatile("cp.async.commit_group;");
}
template<int N>
__device__ __forceinline__ void cp_wait() {
    asm volatile("cp.async.wait_group %0;" :: "n"(N));
}

// ---------------- weight fp32 -> fp16 conversion ----------------
__global__ void wcvt_kernel(const float* __restrict__ wq, const float* __restrict__ wk,
                            const float* __restrict__ wv, const float* __restrict__ wp) {
    int i = blockIdx.x * 256 + threadIdx.x;     // 65536 per weight
    h_w[i          ] = __float2half(wq[i]);
    h_w[i +   CH*CH] = __float2half(wk[i]);
    h_w[i + 2*CH*CH] = __float2half(wv[i]);
    h_w[i + 3*CH*CH] = __float2half(wp[i]);
}

// ---------------- GroupNorm: 3-kernel deterministic split ----------------
// partial: 1024 blocks; each reduces 16384 floats of one (group, segment)
__global__ void gn_partial_kernel(const float* __restrict__ x) {
    const int SEG = CPG*NPOS/GSPLIT;            // 16384
    int grp = blockIdx.x / GSPLIT;
    int seg = blockIdx.x % GSPLIT;
    const float4* px = reinterpret_cast<const float4*>(
        x + (size_t)grp*CPG*NPOS + (size_t)seg*SEG);
    int tid = threadIdx.x;                      // 256
    float s = 0.f, s2 = 0.f;
    #pragma unroll
    for (int i = 0; i < SEG/4/256; i++) {       // 16 iters
        float4 t = px[tid + i*256];
        s  += t.x + t.y + t.z + t.w;
        s2 += t.x*t.x + t.y*t.y + t.z*t.z + t.w*t.w;
    }
    __shared__ float rs[32], rs2[32];
    int lane = tid & 31, wid = tid >> 5;
    #pragma unroll
    for (int o = 16; o > 0; o >>= 1) {
        s  += __shfl_xor_sync(0xffffffffu, s,  o);
        s2 += __shfl_xor_sync(0xffffffffu, s2, o);
    }
    if (lane == 0) { rs[wid] = s; rs2[wid] = s2; }
    __syncthreads();
    if (wid == 0) {
        s  = (lane < 8) ? rs[lane]  : 0.f;
        s2 = (lane < 8) ? rs2[lane] : 0.f;
        #pragma unroll
        for (int o = 4; o > 0; o >>= 1) {
            s  += __shfl_xor_sync(0xffffffffu, s,  o);
            s2 += __shfl_xor_sync(0xffffffffu, s2, o);
        }
        if (lane == 0) {
            g_part[blockIdx.x*2    ] = s;
            g_part[blockIdx.x*2 + 1] = s2;
        }
    }
}

__global__ void gn_stats_kernel() {
    int g = threadIdx.x;                        // 64 groups
    if (g >= BATCH*NGRP) return;
    float s = 0.f, s2 = 0.f;
    #pragma unroll
    for (int i = 0; i < GSPLIT; i++) {
        s  += g_part[(g*GSPLIT + i)*2    ];
        s2 += g_part[(g*GSPLIT + i)*2 + 1];
    }
    const float invN = 1.f / (CPG*NPOS);
    float mean = s * invN;
    float var  = s2 * invN - mean*mean;
    g_stats[g*2    ] = mean;
    g_stats[g*2 + 1] = rsqrtf(var + 1e-5f);
}

// normalize: 8 floats per thread (2 x float4 in, 1 x uint4 of halves out)
__global__ void gn_norm_kernel(const float* __restrict__ x,
                               const float* __restrict__ gamma,
                               const float* __restrict__ beta) {
    size_t base = ((size_t)blockIdx.x*256 + threadIdx.x) * 8;
    int c  = (int)((base / NPOS) & (CH-1));
    int gi = (int)(base / ((size_t)CPG*NPOS));
    float mean = g_stats[gi*2], rstd = g_stats[gi*2+1];
    float ga = gamma[c] * rstd;
    float be = beta[c] - mean * ga;
    const float4* px = reinterpret_cast<const float4*>(x + base);
    float4 a = px[0], b = px[1];
    __half2 h[4];
    h[0] = __floats2half2_rn(a.x*ga+be, a.y*ga+be);
    h[1] = __floats2half2_rn(a.z*ga+be, a.w*ga+be);
    h[2] = __floats2half2_rn(b.x*ga+be, b.y*ga+be);
    h[3] = __floats2half2_rn(b.z*ga+be, b.w*ga+be);
    *reinterpret_cast<uint4*>(&h_xn[base]) = *reinterpret_cast<uint4*>(h);
}

// ---------------- mma / ldmatrix helpers ----------------
__device__ __forceinline__ void mma_f16(float c[4], const unsigned a[4], const unsigned b[2]) {
    asm volatile("mma.sync.aligned.m16n8k16.row.col.f32.f16.f16.f32 "
        "{%0,%1,%2,%3}, {%4,%5,%6,%7}, {%8,%9}, {%0,%1,%2,%3};"
        : "+f"(c[0]), "+f"(c[1]), "+f"(c[2]), "+f"(c[3])
        : "r"(a[0]), "r"(a[1]), "r"(a[2]), "r"(a[3]), "r"(b[0]), "r"(b[1]));
}
__device__ __forceinline__ void ldsm4(unsigned &r0, unsigned &r1, unsigned &r2, unsigned &r3, unsigned addr) {
    asm volatile("ldmatrix.sync.aligned.m8n8.x4.shared.b16 {%0,%1,%2,%3}, [%4];"
        : "=r"(r0), "=r"(r1), "=r"(r2), "=r"(r3) : "r"(addr));
}
__device__ __forceinline__ void ldsm4t(unsigned &r0, unsigned &r1, unsigned &r2, unsigned &r3, unsigned addr) {
    asm volatile("ldmatrix.sync.aligned.m8n8.x4.trans.shared.b16 {%0,%1,%2,%3}, [%4];"
        : "=r"(r0), "=r"(r1), "=r"(r2), "=r"(r3) : "r"(addr));
}

// ---------------- generic batched fp16 tensor-core GEMM ----------------
// 128x128x32 tile, 256 threads (8 warps 2x4), 64x32 warp tile,
// 3-stage cp.async pipeline, 2 CTAs/SM.
template<bool AKM, bool BNM, bool OUTF32>
__global__ __launch_bounds__(256, 2)
void hgemm_kernel(const __half* __restrict__ A, const __half* __restrict__ B,
                  void* __restrict__ Cp,
                  int K, int lda, int ldb, int ldc,
                  long long sA, long long sB, long long sC,
                  float alpha,
                  const float* __restrict__ bias,
                  const float* __restrict__ resid, long long sR)
{
    const int BM = 128, BN = 128;
    constexpr int ASZ = AKM ? 32*136 : 128*40;
    constexpr int BSZ = BNM ? 128*40 : 32*136;
    __shared__ __align__(16) __half As[3][ASZ];
    __shared__ __align__(16) __half Bs[3][BSZ];

    int bz = blockIdx.z;
    A += (size_t)bz * sA;
    B += (size_t)bz * sB;
    int m0 = blockIdx.y * BM;
    int n0 = blockIdx.x * BN;
    int tid = threadIdx.x, lane = tid & 31, warp = tid >> 5;
    int wm = (warp & 1) * 64;
    int wn = (warp >> 1) * 32;

    // global load setup: 2 x 16B per thread per operand per stage
    const __half* aptr[2]; int asmo[2];
    const __half* bptr[2]; int bsmo[2];
    #pragma unroll
    for (int i = 0; i < 2; i++) {
        int idx = tid + i*256;
        if (AKM) { int r = idx >> 4, c = (idx & 15)*8;
                   aptr[i] = A + (size_t)r*lda + m0 + c; asmo[i] = r*136 + c; }
        else     { int r = idx >> 2, c = (idx & 3)*8;
                   aptr[i] = A + (size_t)(m0+r)*lda + c; asmo[i] = r*40 + c; }
        if (BNM) { int r = idx >> 2, c = (idx & 3)*8;
                   bptr[i] = B + (size_t)(n0+r)*ldb + c; bsmo[i] = r*40 + c; }
        else     { int r = idx >> 4, c = (idx & 15)*8;
                   bptr[i] = B + (size_t)r*ldb + n0 + c; bsmo[i] = r*136 + c; }
    }
    const long long stepA = AKM ? (long long)32*lda : 32;
    const long long stepB = BNM ? 32 : (long long)32*ldb;

    unsigned abase = (unsigned)__cvta_generic_to_shared(&As[0][0]);
    unsigned bbase = (unsigned)__cvta_generic_to_shared(&Bs[0][0]);

    // prologue: issue stages 0 and 1
    #pragma unroll
    for (int st = 0; st < 2; st++) {
        #pragma unroll
        for (int i = 0; i < 2; i++) {
            cp_async16(abase + (st*ASZ + asmo[i])*2u, aptr[i]);
            cp_async16(bbase + (st*BSZ + bsmo[i])*2u, bptr[i]);
            aptr[i] += stepA; bptr[i] += stepB;
        }
        cp_commit();
    }

    float acc[4][4][4] = {};
    int nk = K >> 5;

    for (int s = 0; s < nk; s++) {
        cp_wait<1>();
        __syncthreads();

        // issue stage s+2 into buffer (s+2)%3 (freed by sync above)
        if (s + 2 < nk) {
            int st = (s + 2) % 3;
            #pragma unroll
            for (int i = 0; i < 2; i++) {
                cp_async16(abase + (st*ASZ + asmo[i])*2u, aptr[i]);
                cp_async16(bbase + (st*BSZ + bsmo[i])*2u, bptr[i]);
                aptr[i] += stepA; bptr[i] += stepB;
            }
        }
        cp_commit();   // one group per iteration (empty in tail) keeps wait<1> valid

        int cur = s % 3;
        unsigned ab = abase + (unsigned)(cur*ASZ)*2u;
        unsigned bb = bbase + (unsigned)(cur*BSZ)*2u;

        // interleaved k-subslices: small fragment footprint (2 CTA/SM)
        #pragma unroll
        for (int ks = 0; ks < 2; ks++) {
            unsigned af[4][4], bf[4][2];
            #pragma unroll
            for (int mi = 0; mi < 4; mi++) {
                unsigned addr;
                if (AKM) {
                    addr = ab + 2u*(((lane&7) + ((lane>>4)&1)*8 + ks*16)*136
                                     + wm + mi*16 + ((lane>>3)&1)*8);
                    ldsm4t(af[mi][0], af[mi][1], af[mi][2], af[mi][3], addr);
                } else {
                    addr = ab + 2u*((wm + mi*16 + (lane&15))*40 + ks*16 + (lane>>4)*8);
                    ldsm4(af[mi][0], af[mi][1], af[mi][2], af[mi][3], addr);
                }
            }
            #pragma unroll
            for (int bi = 0; bi < 2; bi++) {
                unsigned q0, q1, q2, q3, addr;
                if (BNM) {
                    addr = bb + 2u*((wn + bi*16 + (lane&7) + (lane>>4)*8)*40
                                     + ks*16 + ((lane>>3)&1)*8);
                    ldsm4(q0, q1, q2, q3, addr);
                } else {
                    addr = bb + 2u*(((lane&7) + ((lane>>3)&1)*8 + ks*16)*136
                                     + wn + bi*16 + (lane>>4)*8);
                    ldsm4t(q0, q1, q2, q3, addr);
                }
                bf[bi*2  ][0] = q0; bf[bi*2  ][1] = q1;
                bf[bi*2+1][0] = q2; bf[bi*2+1][1] = q3;
            }
            #pragma unroll
            for (int mi = 0; mi < 4; mi++)
                #pragma unroll
                for (int nj = 0; nj < 4; nj++)
                    mma_f16(acc[mi][nj], af[mi], bf[nj]);
        }
    }

    // epilogue
    if (OUTF32) {
        float* C = (float*)Cp + (size_t)bz * sC;
        const float* R = resid ? resid + (size_t)bz * sR : nullptr;
        #pragma unroll
        for (int mi = 0; mi < 4; mi++) {
            #pragma unroll
            for (int h = 0; h < 2; h++) {
                int m = m0 + wm + mi*16 + (lane >> 2) + h*8;
                float bv = bias ? bias[m] : 0.f;
                #pragma unroll
                for (int nj = 0; nj < 4; nj++) {
                    int n = n0 + wn + nj*8 + 2*(lane & 3);
                    float2 val;
                    val.x = acc[mi][nj][h*2+0] * alpha + bv;
                    val.y = acc[mi][nj][h*2+1] * alpha + bv;
                    if (R) {
                        val.x += R[(size_t)m*ldc + n];
                        val.y += R[(size_t)m*ldc + n + 1];
                    }
                    *reinterpret_cast<float2*>(&C[(size_t)m*ldc + n]) = val;
                }
            }
        }
    } else {
        __half* C = (__half*)Cp + (size_t)bz * sC;
        #pragma unroll
        for (int mi = 0; mi < 4; mi++) {
            #pragma unroll
            for (int h = 0; h < 2; h++) {
                int m = m0 + wm + mi*16 + (lane >> 2) + h*8;
                float bv = bias ? bias[m] : 0.f;
                #pragma unroll
                for (int nj = 0; nj < 4; nj++) {
                    int n = n0 + wn + nj*8 + 2*(lane & 3);
                    __half2 hv = __floats2half2_rn(acc[mi][nj][h*2+0]*alpha + bv,
                                                   acc[mi][nj][h*2+1]*alpha + bv);
                    *reinterpret_cast<__half2*>(&C[(size_t)m*ldc + n]) = hv;
                }
            }
        }
    }
}

// ---------------- row softmax over h_attn[8,4096,4096] (fp16 in/out) ----------------
__global__ void softmax_kernel(__half* __restrict__ attn) {
    size_t row = blockIdx.x;
    __half* p = attn + row * NPOS;
    uint4* pv = reinterpret_cast<uint4*>(p);
    int tid  = threadIdx.x;        // 256 threads, 16 halves each (2 x uint4)
    int lane = tid & 31, wid = tid >> 5;

    uint4 u[2];
    u[0] = pv[tid];
    u[1] = pv[tid + 256];
    float v[16];
    #pragma unroll
    for (int i = 0; i < 2; i++) {
        const __half2* h2 = reinterpret_cast<const __half2*>(&u[i]);
        #pragma unroll
        for (int j = 0; j < 4; j++) {
            float2 f = __half22float2(h2[j]);
            v[i*8 + j*2 + 0] = f.x;
            v[i*8 + j*2 + 1] = f.y;
        }
    }

    float mx = -CUDART_INF_F;
    #pragma unroll
    for (int i = 0; i < 16; i++) mx = fmaxf(mx, v[i]);

    __shared__ float red[32];
    #pragma unroll
    for (int o = 16; o > 0; o >>= 1) mx = fmaxf(mx, __shfl_xor_sync(0xffffffffu, mx, o));
    if (lane == 0) red[wid] = mx;
    __syncthreads();
    if (wid == 0) {
        float t = (lane < 8) ? red[lane] : -CUDART_INF_F;
        #pragma unroll
        for (int o = 4; o > 0; o >>= 1) t = fmaxf(t, __shfl_xor_sync(0xffffffffu, t, o));
        if (lane == 0) red[0] = t;
    }
    __syncthreads();
    mx = red[0];

    float s = 0.f;
    #pragma unroll
    for (int i = 0; i < 16; i++) { v[i] = __expf(v[i] - mx); s += v[i]; }
    __shared__ float red2[32];
    #pragma unroll
    for (int o = 16; o > 0; o >>= 1) s += __shfl_xor_sync(0xffffffffu, s, o);
    if (lane == 0) red2[wid] = s;
    __syncthreads();
    if (wid == 0) {
        float t = (lane < 8) ? red2[lane] : 0.f;
        #pragma unroll
        for (int o = 4; o > 0; o >>= 1) t += __shfl_xor_sync(0xffffffffu, t, o);
        if (lane == 0) red2[0] = t;
    }
    __syncthreads();
    float inv = 1.f / red2[0];

    #pragma unroll
    for (int i = 0; i < 2; i++) {
        __half2* h2 = reinterpret_cast<__half2*>(&u[i]);
        #pragma unroll
        for (int j = 0; j < 4; j++)
            h2[j] = __floats2half2_rn(v[i*8+j*2+0]*inv, v[i*8+j*2+1]*inv);
    }
    pv[tid]       = u[0];
    pv[tid + 256] = u[1];
}

// ---------------- launcher ----------------
extern "C" void kernel_launch(void* const* d_in, const int* in_sizes, int n_in,
                              void* d_out, int out_size) {
    const float* x     = (const float*)d_in[0];
    const float* gamma = (const float*)d_in[1];
    const float* beta  = (const float*)d_in[2];
    const float* wq    = (const float*)d_in[3];
    const float* bq    = (const float*)d_in[4];
    const float* wk    = (const float*)d_in[5];
    const float* bk    = (const float*)d_in[6];
    const float* wv    = (const float*)d_in[7];
    const float* bv    = (const float*)d_in[8];
    const float* wp    = (const float*)d_in[9];
    const float* bp    = (const float*)d_in[10];
    float* out = (float*)d_out;

    __half *xn, *q, *k, *v, *o, *attn, *w;
    cudaGetSymbolAddress((void**)&xn,   h_xn);
    cudaGetSymbolAddress((void**)&q,    h_q);
    cudaGetSymbolAddress((void**)&k,    h_k);
    cudaGetSymbolAddress((void**)&v,    h_v);
    cudaGetSymbolAddress((void**)&o,    h_o);
    cudaGetSymbolAddress((void**)&attn, h_attn);
    cudaGetSymbolAddress((void**)&w,    h_w);

    // 0. weights fp32 -> fp16
    wcvt_kernel<<<CH*CH/256, 256>>>(wq, wk, wv, wp);

    // 1. GroupNorm -> fp16 xn (3-kernel split, full-chip parallel)
    gn_partial_kernel<<<BATCH*NGRP*GSPLIT, 256>>>(x);
    gn_stats_kernel<<<1, 64>>>();
    gn_norm_kernel<<<(BATCH*CH*NPOS)/(256*8), 256>>>(x, gamma, beta);

    const long long sX  = (long long)CH * NPOS;
    const long long sAt = (long long)NPOS * NPOS;

    // 2. Q/K/V projections: W[256,256] x Xn[256,4096] -> fp16
    dim3 gq(NPOS/128, CH/128, BATCH);
    hgemm_kernel<false,false,false><<<gq,256>>>(w,           xn, q, CH, CH, NPOS, NPOS,
                                                0, sX, sX, 1.f, bq, nullptr, 0);
    hgemm_kernel<false,false,false><<<gq,256>>>(w +   CH*CH, xn, k, CH, CH, NPOS, NPOS,
                                                0, sX, sX, 1.f, bk, nullptr, 0);
    hgemm_kernel<false,false,false><<<gq,256>>>(w + 2*CH*CH, xn, v, CH, CH, NPOS, NPOS,
                                                0, sX, sX, 1.f, bv, nullptr, 0);

    // 3. S = (1/16) * Q^T K  (A = q [c][i] k-major, B = k [c][j])
    dim3 gs(NPOS/128, NPOS/128, BATCH);
    hgemm_kernel<true,false,false><<<gs,256>>>(q, k, attn, CH, NPOS, NPOS, NPOS,
                                               sX, sX, sAt, 0.0625f, nullptr, nullptr, 0);

    // 4. softmax over last dim
    softmax_kernel<<<BATCH*NPOS, 256>>>(attn);

    // 5. O = V * A^T  (A = v [c][j], B = attn [i][j] n-major)
    hgemm_kernel<false,true,false><<<gq,256>>>(v, attn, o, NPOS, NPOS, NPOS, NPOS,
                                               sX, sAt, sX, 1.f, nullptr, nullptr, 0);

    // 6. out = Wp*O + bp + x (residual, fp32 out)
    hgemm_kernel<false,false,true><<<gq,256>>>(w + 3*CH*CH, o, out, CH, CH, NPOS, NPOS,
                                               0, sX, sX, 1.f, bp, x, sX);
}

// round 11
// speedup vs baseline: 10.5739x; 1.1241x over previous
#include <cuda_runtime.h>
#include <cuda_fp16.h>
#include <math_constants.h>

#define BATCH 8
#define CH    256
#define NPOS  4096      // 64*64
#define NGRP  8
#define CPG   (CH/NGRP) // 32
#define GSPLIT 8

#define BR 128
#define BC 64
// softmax scale folded into log2 domain: (1/16) * log2(e)
#define SCALE_LOG2 0.09016844f

// ---------------- scratch (device globals; no allocation allowed) ----------------
__device__ __align__(16) __half h_xn [(size_t)BATCH*CH*NPOS];
__device__ __align__(16) __half h_q  [(size_t)BATCH*CH*NPOS];
__device__ __align__(16) __half h_k  [(size_t)BATCH*CH*NPOS];
__device__ __align__(16) __half h_v  [(size_t)BATCH*CH*NPOS];
__device__ __align__(16) __half h_o  [(size_t)BATCH*CH*NPOS];   // [b][i][c] layout!
__device__ __align__(16) __half h_w  [4*(size_t)CH*CH];
__device__ float g_part [BATCH*NGRP*GSPLIT*2];
__device__ float g_stats[BATCH*NGRP*2];

// ---------------- small helpers ----------------
__device__ __forceinline__ void cp_async16(unsigned dst, const void* src) {
    asm volatile("cp.async.cg.shared.global [%0], [%1], 16;" :: "r"(dst), "l"(src));
}
__device__ __forceinline__ void cp_commit() {
    asm volatile("cp.async.commit_group;");
}
template<int N>
__device__ __forceinline__ void cp_wait() {
    asm volatile("cp.async.wait_group %0;" :: "n"(N));
}
__device__ __forceinline__ float fexp2(float x) {
    float y;
    asm("ex2.approx.f32 %0, %1;" : "=f"(y) : "f"(x));
    return y;
}
__device__ __forceinline__ void mma_f16(float c[4], const unsigned a[4], const unsigned b[2]) {
    asm volatile("mma.sync.aligned.m16n8k16.row.col.f32.f16.f16.f32 "
        "{%0,%1,%2,%3}, {%4,%5,%6,%7}, {%8,%9}, {%0,%1,%2,%3};"
        : "+f"(c[0]), "+f"(c[1]), "+f"(c[2]), "+f"(c[3])
        : "r"(a[0]), "r"(a[1]), "r"(a[2]), "r"(a[3]), "r"(b[0]), "r"(b[1]));
}
__device__ __forceinline__ void ldsm4(unsigned &r0, unsigned &r1, unsigned &r2, unsigned &r3, unsigned addr) {
    asm volatile("ldmatrix.sync.aligned.m8n8.x4.shared.b16 {%0,%1,%2,%3}, [%4];"
        : "=r"(r0), "=r"(r1), "=r"(r2), "=r"(r3) : "r"(addr));
}
__device__ __forceinline__ void ldsm4t(unsigned &r0, unsigned &r1, unsigned &r2, unsigned &r3, unsigned addr) {
    asm volatile("ldmatrix.sync.aligned.m8n8.x4.trans.shared.b16 {%0,%1,%2,%3}, [%4];"
        : "=r"(r0), "=r"(r1), "=r"(r2), "=r"(r3) : "r"(addr));
}

// ---------------- weight fp32 -> fp16 conversion ----------------
__global__ void wcvt_kernel(const float* __restrict__ wq, const float* __restrict__ wk,
                            const float* __restrict__ wv, const float* __restrict__ wp) {
    int i = blockIdx.x * 256 + threadIdx.x;
    h_w[i          ] = __float2half(wq[i]);
    h_w[i +   CH*CH] = __float2half(wk[i]);
    h_w[i + 2*CH*CH] = __float2half(wv[i]);
    h_w[i + 3*CH*CH] = __float2half(wp[i]);
}

// ---------------- GroupNorm: 3-kernel deterministic split ----------------
__global__ void gn_partial_kernel(const float* __restrict__ x) {
    const int SEG = CPG*NPOS/GSPLIT;            // 16384
    int grp = blockIdx.x / GSPLIT;
    int seg = blockIdx.x % GSPLIT;
    const float4* px = reinterpret_cast<const float4*>(
        x + (size_t)grp*CPG*NPOS + (size_t)seg*SEG);
    int tid = threadIdx.x;
    float s = 0.f, s2 = 0.f;
    #pragma unroll
    for (int i = 0; i < SEG/4/256; i++) {
        float4 t = px[tid + i*256];
        s  += t.x + t.y + t.z + t.w;
        s2 += t.x*t.x + t.y*t.y + t.z*t.z + t.w*t.w;
    }
    __shared__ float rs[32], rs2[32];
    int lane = tid & 31, wid = tid >> 5;
    #pragma unroll
    for (int o = 16; o > 0; o >>= 1) {
        s  += __shfl_xor_sync(0xffffffffu, s,  o);
        s2 += __shfl_xor_sync(0xffffffffu, s2, o);
    }
    if (lane == 0) { rs[wid] = s; rs2[wid] = s2; }
    __syncthreads();
    if (wid == 0) {
        s  = (lane < 8) ? rs[lane]  : 0.f;
        s2 = (lane < 8) ? rs2[lane] : 0.f;
        #pragma unroll
        for (int o = 4; o > 0; o >>= 1) {
            s  += __shfl_xor_sync(0xffffffffu, s,  o);
            s2 += __shfl_xor_sync(0xffffffffu, s2, o);
        }
        if (lane == 0) {
            g_part[blockIdx.x*2    ] = s;
            g_part[blockIdx.x*2 + 1] = s2;
        }
    }
}

__global__ void gn_stats_kernel() {
    int g = threadIdx.x;
    if (g >= BATCH*NGRP) return;
    float s = 0.f, s2 = 0.f;
    #pragma unroll
    for (int i = 0; i < GSPLIT; i++) {
        s  += g_part[(g*GSPLIT + i)*2    ];
        s2 += g_part[(g*GSPLIT + i)*2 + 1];
    }
    const float invN = 1.f / (CPG*NPOS);
    float mean = s * invN;
    float var  = s2 * invN - mean*mean;
    g_stats[g*2    ] = mean;
    g_stats[g*2 + 1] = rsqrtf(var + 1e-5f);
}

__global__ void gn_norm_kernel(const float* __restrict__ x,
                               const float* __restrict__ gamma,
                               const float* __restrict__ beta) {
    size_t base = ((size_t)blockIdx.x*256 + threadIdx.x) * 8;
    int c  = (int)((base / NPOS) & (CH-1));
    int gi = (int)(base / ((size_t)CPG*NPOS));
    float mean = g_stats[gi*2], rstd = g_stats[gi*2+1];
    float ga = gamma[c] * rstd;
    float be = beta[c] - mean * ga;
    const float4* px = reinterpret_cast<const float4*>(x + base);
    float4 a = px[0], b = px[1];
    __half2 h[4];
    h[0] = __floats2half2_rn(a.x*ga+be, a.y*ga+be);
    h[1] = __floats2half2_rn(a.z*ga+be, a.w*ga+be);
    h[2] = __floats2half2_rn(b.x*ga+be, b.y*ga+be);
    h[3] = __floats2half2_rn(b.z*ga+be, b.w*ga+be);
    *reinterpret_cast<uint4*>(&h_xn[base]) = *reinterpret_cast<uint4*>(h);
}

// ---------------- generic batched fp16 tensor-core GEMM (projections) ----------------
template<bool AKM, bool BNM, bool OUTF32>
__global__ __launch_bounds__(256, 2)
void hgemm_kernel(const __half* __restrict__ A, const __half* __restrict__ B,
                  void* __restrict__ Cp,
                  int K, int lda, int ldb, int ldc,
                  long long sA, long long sB, long long sC,
                  float alpha,
                  const float* __restrict__ bias,
                  const float* __restrict__ resid, long long sR)
{
    const int BM = 128, BN = 128;
    constexpr int ASZ = AKM ? 32*136 : 128*40;
    constexpr int BSZ = BNM ? 128*40 : 32*136;
    __shared__ __align__(16) __half As[3][ASZ];
    __shared__ __align__(16) __half Bs[3][BSZ];

    int bz = blockIdx.z;
    A += (size_t)bz * sA;
    B += (size_t)bz * sB;
    int m0 = blockIdx.y * BM;
    int n0 = blockIdx.x * BN;
    int tid = threadIdx.x, lane = tid & 31, warp = tid >> 5;
    int wm = (warp & 1) * 64;
    int wn = (warp >> 1) * 32;

    const __half* aptr[2]; int asmo[2];
    const __half* bptr[2]; int bsmo[2];
    #pragma unroll
    for (int i = 0; i < 2; i++) {
        int idx = tid + i*256;
        if (AKM) { int r = idx >> 4, c = (idx & 15)*8;
                   aptr[i] = A + (size_t)r*lda + m0 + c; asmo[i] = r*136 + c; }
        else     { int r = idx >> 2, c = (idx & 3)*8;
                   aptr[i] = A + (size_t)(m0+r)*lda + c; asmo[i] = r*40 + c; }
        if (BNM) { int r = idx >> 2, c = (idx & 3)*8;
                   bptr[i] = B + (size_t)(n0+r)*ldb + c; bsmo[i] = r*40 + c; }
        else     { int r = idx >> 4, c = (idx & 15)*8;
                   bptr[i] = B + (size_t)r*ldb + n0 + c; bsmo[i] = r*136 + c; }
    }
    const long long stepA = AKM ? (long long)32*lda : 32;
    const long long stepB = BNM ? 32 : (long long)32*ldb;

    unsigned abase = (unsigned)__cvta_generic_to_shared(&As[0][0]);
    unsigned bbase = (unsigned)__cvta_generic_to_shared(&Bs[0][0]);

    #pragma unroll
    for (int st = 0; st < 2; st++) {
        #pragma unroll
        for (int i = 0; i < 2; i++) {
            cp_async16(abase + (st*ASZ + asmo[i])*2u, aptr[i]);
            cp_async16(bbase + (st*BSZ + bsmo[i])*2u, bptr[i]);
            aptr[i] += stepA; bptr[i] += stepB;
        }
        cp_commit();
    }

    float acc[4][4][4] = {};
    int nk = K >> 5;

    for (int s = 0; s < nk; s++) {
        cp_wait<1>();
        __syncthreads();

        if (s + 2 < nk) {
            int st = (s + 2) % 3;
            #pragma unroll
            for (int i = 0; i < 2; i++) {
                cp_async16(abase + (st*ASZ + asmo[i])*2u, aptr[i]);
                cp_async16(bbase + (st*BSZ + bsmo[i])*2u, bptr[i]);
                aptr[i] += stepA; bptr[i] += stepB;
            }
        }
        cp_commit();

        int cur = s % 3;
        unsigned ab = abase + (unsigned)(cur*ASZ)*2u;
        unsigned bb = bbase + (unsigned)(cur*BSZ)*2u;

        #pragma unroll
        for (int ks = 0; ks < 2; ks++) {
            unsigned af[4][4], bf[4][2];
            #pragma unroll
            for (int mi = 0; mi < 4; mi++) {
                unsigned addr;
                if (AKM) {
                    addr = ab + 2u*(((lane&7) + ((lane>>4)&1)*8 + ks*16)*136
                                     + wm + mi*16 + ((lane>>3)&1)*8);
                    ldsm4t(af[mi][0], af[mi][1], af[mi][2], af[mi][3], addr);
                } else {
                    addr = ab + 2u*((wm + mi*16 + (lane&15))*40 + ks*16 + (lane>>4)*8);
                    ldsm4(af[mi][0], af[mi][1], af[mi][2], af[mi][3], addr);
                }
            }
            #pragma unroll
            for (int bi = 0; bi < 2; bi++) {
                unsigned q0, q1, q2, q3, addr;
                if (BNM) {
                    addr = bb + 2u*((wn + bi*16 + (lane&7) + (lane>>4)*8)*40
                                     + ks*16 + ((lane>>3)&1)*8);
                    ldsm4(q0, q1, q2, q3, addr);
                } else {
                    addr = bb + 2u*(((lane&7) + ((lane>>3)&1)*8 + ks*16)*136
                                     + wn + bi*16 + (lane>>4)*8);
                    ldsm4t(q0, q1, q2, q3, addr);
                }
                bf[bi*2  ][0] = q0; bf[bi*2  ][1] = q1;
                bf[bi*2+1][0] = q2; bf[bi*2+1][1] = q3;
            }
            #pragma unroll
            for (int mi = 0; mi < 4; mi++)
                #pragma unroll
                for (int nj = 0; nj < 4; nj++)
                    mma_f16(acc[mi][nj], af[mi], bf[nj]);
        }
    }

    if (OUTF32) {
        float* C = (float*)Cp + (size_t)bz * sC;
        const float* R = resid ? resid + (size_t)bz * sR : nullptr;
        #pragma unroll
        for (int mi = 0; mi < 4; mi++) {
            #pragma unroll
            for (int h = 0; h < 2; h++) {
                int m = m0 + wm + mi*16 + (lane >> 2) + h*8;
                float bv = bias ? bias[m] : 0.f;
                #pragma unroll
                for (int nj = 0; nj < 4; nj++) {
                    int n = n0 + wn + nj*8 + 2*(lane & 3);
                    float2 val;
                    val.x = acc[mi][nj][h*2+0] * alpha + bv;
                    val.y = acc[mi][nj][h*2+1] * alpha + bv;
                    if (R) {
                        val.x += R[(size_t)m*ldc + n];
                        val.y += R[(size_t)m*ldc + n + 1];
                    }
                    *reinterpret_cast<float2*>(&C[(size_t)m*ldc + n]) = val;
                }
            }
        }
    } else {
        __half* C = (__half*)Cp + (size_t)bz * sC;
        #pragma unroll
        for (int mi = 0; mi < 4; mi++) {
            #pragma unroll
            for (int h = 0; h < 2; h++) {
                int m = m0 + wm + mi*16 + (lane >> 2) + h*8;
                float bv = bias ? bias[m] : 0.f;
                #pragma unroll
                for (int nj = 0; nj < 4; nj++) {
                    int n = n0 + wn + nj*8 + 2*(lane & 3);
                    __half2 hv = __floats2half2_rn(acc[mi][nj][h*2+0]*alpha + bv,
                                                   acc[mi][nj][h*2+1]*alpha + bv);
                    *reinterpret_cast<__half2*>(&C[(size_t)m*ldc + n]) = hv;
                }
            }
        }
    }
}

// ---------------- fused flash attention ----------------
// grid (NPOS/BR, BATCH), 256 threads (8 warps), 1 CTA/SM.
// Q/K/V stored [b][c][i] fp16. Output h_o stored [b][i][c] fp16 (for BNM proj).
// Each warp owns 16 Q-rows x full C=256. Online softmax, O accum in mma C frags.
#define QS_OFF  0
#define QS_LD   136
#define KS_OFF  34816              // 256*136
#define KS_LD   72
#define KS_SZ   (256*72)           // 18432 halves
#define VS_OFF  (KS_OFF + 2*KS_SZ)
#define VS_SZ   KS_SZ
#define FLASH_SMEM ((KS_OFF + 2*KS_SZ + 2*VS_SZ)*2)   // 217088 bytes
#define OS_LD   264

__global__ __launch_bounds__(256, 1)
void flash_kernel(const __half* __restrict__ Q, const __half* __restrict__ Kg,
                  const __half* __restrict__ Vg, __half* __restrict__ Og)
{
    extern __shared__ __half smem[];
    int b  = blockIdx.y;
    int i0 = blockIdx.x * BR;
    const size_t sX = (size_t)CH * NPOS;
    Q  += (size_t)b*sX; Kg += (size_t)b*sX; Vg += (size_t)b*sX;

    int tid = threadIdx.x, lane = tid & 31, warp = tid >> 5;
    unsigned sbase = (unsigned)__cvta_generic_to_shared(smem);

    // prologue: Q tile + K/V stage 0 (group 0), K/V stage 1 (group 1)
    #pragma unroll
    for (int i = 0; i < 16; i++) {
        int idx = tid + i*256;
        int c = idx >> 4, col = (idx & 15)*8;
        cp_async16(sbase + (unsigned)(QS_OFF + c*QS_LD + col)*2u,
                   Q + (size_t)c*NPOS + i0 + col);
    }
    #pragma unroll
    for (int i = 0; i < 8; i++) {
        int idx = tid + i*256;
        int c = idx >> 3, col = (idx & 7)*8;
        cp_async16(sbase + (unsigned)(KS_OFF + c*KS_LD + col)*2u,
                   Kg + (size_t)c*NPOS + col);
        cp_async16(sbase + (unsigned)(VS_OFF + c*KS_LD + col)*2u,
                   Vg + (size_t)c*NPOS + col);
    }
    cp_commit();
    #pragma unroll
    for (int i = 0; i < 8; i++) {
        int idx = tid + i*256;
        int c = idx >> 3, col = (idx & 7)*8;
        cp_async16(sbase + (unsigned)(KS_OFF + KS_SZ + c*KS_LD + col)*2u,
                   Kg + (size_t)c*NPOS + BC + col);
        cp_async16(sbase + (unsigned)(VS_OFF + VS_SZ + c*KS_LD + col)*2u,
                   Vg + (size_t)c*NPOS + BC + col);
    }
    cp_commit();

    float oacc[32][4] = {};        // 32 c-tiles (8 wide) of 16-row warp band
    float m0 = -CUDART_INF_F, m1 = -CUDART_INF_F;
    float l0 = 0.f, l1 = 0.f;

    const int NITER = NPOS / BC;   // 64
    for (int s = 0; s < NITER; s++) {
        cp_wait<1>();
        __syncthreads();
        int cur = s & 1;
        unsigned qb = sbase;
        unsigned kb = sbase + (unsigned)(KS_OFF + cur*KS_SZ)*2u;
        unsigned vb = sbase + (unsigned)(VS_OFF + cur*VS_SZ)*2u;

        // ---- S(16x64) = Q_warp^T K_tile, K-dim = C = 256
        float sacc[8][4] = {};
        #pragma unroll
        for (int ks = 0; ks < 16; ks++) {
            unsigned af[4];
            unsigned aaddr = qb + 2u*(((lane&7) + ((lane>>4)&1)*8 + ks*16)*QS_LD
                                       + warp*16 + ((lane>>3)&1)*8);
            ldsm4t(af[0], af[1], af[2], af[3], aaddr);
            #pragma unroll
            for (int bi = 0; bi < 4; bi++) {
                unsigned q0, q1, q2, q3;
                unsigned baddr = kb + 2u*(((lane&7) + ((lane>>3)&1)*8 + ks*16)*KS_LD
                                           + bi*16 + (lane>>4)*8);
                ldsm4t(q0, q1, q2, q3, baddr);
                unsigned bf0[2] = {q0, q1}, bf1[2] = {q2, q3};
                mma_f16(sacc[bi*2],   af, bf0);
                mma_f16(sacc[bi*2+1], af, bf1);
            }
        }

        // ---- online softmax (rows g = lane>>2 and g+8; quad = lane&3)
        float rmax0 = -CUDART_INF_F, rmax1 = -CUDART_INF_F;
        #pragma unroll
        for (int nt = 0; nt < 8; nt++) {
            rmax0 = fmaxf(rmax0, fmaxf(sacc[nt][0], sacc[nt][1]));
            rmax1 = fmaxf(rmax1, fmaxf(sacc[nt][2], sacc[nt][3]));
        }
        rmax0 = fmaxf(rmax0, __shfl_xor_sync(0xffffffffu, rmax0, 1));
        rmax0 = fmaxf(rmax0, __shfl_xor_sync(0xffffffffu, rmax0, 2));
        rmax1 = fmaxf(rmax1, __shfl_xor_sync(0xffffffffu, rmax1, 1));
        rmax1 = fmaxf(rmax1, __shfl_xor_sync(0xffffffffu, rmax1, 2));
        float mn0 = fmaxf(m0, rmax0 * SCALE_LOG2);
        float mn1 = fmaxf(m1, rmax1 * SCALE_LOG2);
        float corr0 = fexp2(m0 - mn0);
        float corr1 = fexp2(m1 - mn1);
        m0 = mn0; m1 = mn1;

        float rs0 = 0.f, rs1 = 0.f;
        unsigned pa[4][4];
        #pragma unroll
        for (int kt = 0; kt < 4; kt++) {
            float e00 = fexp2(sacc[2*kt  ][0]*SCALE_LOG2 - mn0);
            float e01 = fexp2(sacc[2*kt  ][1]*SCALE_LOG2 - mn0);
            float e02 = fexp2(sacc[2*kt  ][2]*SCALE_LOG2 - mn1);
            float e03 = fexp2(sacc[2*kt  ][3]*SCALE_LOG2 - mn1);
            float e10 = fexp2(sacc[2*kt+1][0]*SCALE_LOG2 - mn0);
            float e11 = fexp2(sacc[2*kt+1][1]*SCALE_LOG2 - mn0);
            float e12 = fexp2(sacc[2*kt+1][2]*SCALE_LOG2 - mn1);
            float e13 = fexp2(sacc[2*kt+1][3]*SCALE_LOG2 - mn1);
            rs0 += e00 + e01 + e10 + e11;
            rs1 += e02 + e03 + e12 + e13;
            __half2 h;
            h = __floats2half2_rn(e00, e01); pa[kt][0] = *(unsigned*)&h;
            h = __floats2half2_rn(e02, e03); pa[kt][1] = *(unsigned*)&h;
            h = __floats2half2_rn(e10, e11); pa[kt][2] = *(unsigned*)&h;
            h = __floats2half2_rn(e12, e13); pa[kt][3] = *(unsigned*)&h;
        }
        rs0 += __shfl_xor_sync(0xffffffffu, rs0, 1);
        rs0 += __shfl_xor_sync(0xffffffffu, rs0, 2);
        rs1 += __shfl_xor_sync(0xffffffffu, rs1, 1);
        rs1 += __shfl_xor_sync(0xffffffffu, rs1, 2);
        l0 = l0*corr0 + rs0;
        l1 = l1*corr1 + rs1;
        #pragma unroll
        for (int nt = 0; nt < 32; nt++) {
            oacc[nt][0] *= corr0; oacc[nt][1] *= corr0;
            oacc[nt][2] *= corr1; oacc[nt][3] *= corr1;
        }

        // ---- O(16x256) += P(16x64) V^T  (B from Vs[c][j], n-major)
        #pragma unroll
        for (int kt = 0; kt < 4; kt++) {
            #pragma unroll
            for (int bi = 0; bi < 16; bi++) {
                unsigned q0, q1, q2, q3;
                unsigned baddr = vb + 2u*((bi*16 + (lane&7) + (lane>>4)*8)*KS_LD
                                           + kt*16 + ((lane>>3)&1)*8);
                ldsm4(q0, q1, q2, q3, baddr);
                unsigned bf0[2] = {q0, q1}, bf1[2] = {q2, q3};
                mma_f16(oacc[bi*2],   pa[kt], bf0);
                mma_f16(oacc[bi*2+1], pa[kt], bf1);
            }
        }

        __syncthreads();
        // prefetch stage s+2 into buffer s&1 (just finished reading)
        if (s + 2 < NITER) {
            int st = s & 1;
            int j0 = (s + 2) * BC;
            #pragma unroll
            for (int i = 0; i < 8; i++) {
                int idx = tid + i*256;
                int c = idx >> 3, col = (idx & 7)*8;
                cp_async16(sbase + (unsigned)(KS_OFF + st*KS_SZ + c*KS_LD + col)*2u,
                           Kg + (size_t)c*NPOS + j0 + col);
                cp_async16(sbase + (unsigned)(VS_OFF + st*VS_SZ + c*KS_LD + col)*2u,
                           Vg + (size_t)c*NPOS + j0 + col);
            }
        }
        cp_commit();
    }

    // ---- epilogue: normalize, stage [i][c] in SMEM (reuse Q region), coalesced store
    float inv0 = 1.f / l0, inv1 = 1.f / l1;
    int g = lane >> 2, t = lane & 3;
    #pragma unroll
    for (int nt = 0; nt < 32; nt++) {
        int c = nt*8 + 2*t;
        __half2 h0 = __floats2half2_rn(oacc[nt][0]*inv0, oacc[nt][1]*inv0);
        __half2 h1 = __floats2half2_rn(oacc[nt][2]*inv1, oacc[nt][3]*inv1);
        *reinterpret_cast<__half2*>(&smem[(warp*16 + g    )*OS_LD + c]) = h0;
        *reinterpret_cast<__half2*>(&smem[(warp*16 + g + 8)*OS_LD + c]) = h1;
    }
    __syncthreads();
    __half* Ob = Og + (size_t)b*sX + (size_t)i0*CH;
    #pragma unroll
    for (int i = 0; i < 16; i++) {
        int idx = tid + i*256;
        int row = idx >> 5, col = (idx & 31)*8;
        *reinterpret_cast<uint4*>(&Ob[(size_t)row*CH + col]) =
            *reinterpret_cast<uint4*>(&smem[row*OS_LD + col]);
    }
}

// ---------------- launcher ----------------
extern "C" void kernel_launch(void* const* d_in, const int* in_sizes, int n_in,
                              void* d_out, int out_size) {
    const float* x     = (const float*)d_in[0];
    const float* gamma = (const float*)d_in[1];
    const float* beta  = (const float*)d_in[2];
    const float* wq    = (const float*)d_in[3];
    const float* bq    = (const float*)d_in[4];
    const float* wk    = (const float*)d_in[5];
    const float* bk    = (const float*)d_in[6];
    const float* wv    = (const float*)d_in[7];
    const float* bv    = (const float*)d_in[8];
    const float* wp    = (const float*)d_in[9];
    const float* bp    = (const float*)d_in[10];
    float* out = (float*)d_out;

    __half *xn, *q, *k, *v, *o, *w;
    cudaGetSymbolAddress((void**)&xn, h_xn);
    cudaGetSymbolAddress((void**)&q,  h_q);
    cudaGetSymbolAddress((void**)&k,  h_k);
    cudaGetSymbolAddress((void**)&v,  h_v);
    cudaGetSymbolAddress((void**)&o,  h_o);
    cudaGetSymbolAddress((void**)&w,  h_w);

    static bool attr_set = false;
    if (!attr_set) {
        cudaFuncSetAttribute(flash_kernel,
                             cudaFuncAttributeMaxDynamicSharedMemorySize, FLASH_SMEM);
        attr_set = true;
    }

    // 0. weights fp32 -> fp16
    wcvt_kernel<<<CH*CH/256, 256>>>(wq, wk, wv, wp);

    // 1. GroupNorm -> fp16 xn
    gn_partial_kernel<<<BATCH*NGRP*GSPLIT, 256>>>(x);
    gn_stats_kernel<<<1, 64>>>();
    gn_norm_kernel<<<(BATCH*CH*NPOS)/(256*8), 256>>>(x, gamma, beta);

    const long long sX = (long long)CH * NPOS;

    // 2. Q/K/V projections: W[256,256] x Xn[256,4096] -> fp16 [c][i]
    dim3 gq(NPOS/128, CH/128, BATCH);
    hgemm_kernel<false,false,false><<<gq,256>>>(w,           xn, q, CH, CH, NPOS, NPOS,
                                                0, sX, sX, 1.f, bq, nullptr, 0);
    hgemm_kernel<false,false,false><<<gq,256>>>(w +   CH*CH, xn, k, CH, CH, NPOS, NPOS,
                                                0, sX, sX, 1.f, bk, nullptr, 0);
    hgemm_kernel<false,false,false><<<gq,256>>>(w + 2*CH*CH, xn, v, CH, CH, NPOS, NPOS,
                                                0, sX, sX, 1.f, bv, nullptr, 0);

    // 3-5. fused flash attention -> o [i][c]
    dim3 gf(NPOS/BR, BATCH);
    flash_kernel<<<gf, 256, FLASH_SMEM>>>(q, k, v, o);

    // 6. out = Wp*O + bp + x (residual, fp32 out); O is n-major (BNM)
    hgemm_kernel<false,true,true><<<gq,256>>>(w + 3*CH*CH, o, out, CH, CH, CH, NPOS,
                                              0, sX, sX, 1.f, bp, x, sX);
}

// round 16
// speedup vs baseline: 10.5979x; 1.0023x over previous
#include <cuda_runtime.h>
#include <cuda_fp16.h>
#include <math_constants.h>

#define BATCH 8
#define CH    256
#define NPOS  4096      // 64*64
#define NGRP  8
#define CPG   (CH/NGRP) // 32
#define GSPLIT 8

#define BR 128
#define BC 64
// softmax scale folded into log2 domain: (1/16) * log2(e)
#define SCALE_LOG2 0.09016844f

// ---------------- scratch (device globals; no allocation allowed) ----------------
__device__ __align__(16) __half h_xn [(size_t)BATCH*CH*NPOS];
__device__ __align__(16) __half h_q  [(size_t)BATCH*CH*NPOS];
__device__ __align__(16) __half h_k  [(size_t)BATCH*CH*NPOS];
__device__ __align__(16) __half h_v  [(size_t)BATCH*CH*NPOS];
__device__ __align__(16) __half h_o  [(size_t)BATCH*CH*NPOS];   // [b][i][c] layout!
__device__ __align__(16) __half h_w  [4*(size_t)CH*CH];
__device__ float g_part [BATCH*NGRP*GSPLIT*2];
__device__ float g_stats[BATCH*NGRP*2];

// ---------------- small helpers ----------------
__device__ __forceinline__ void cp_async16(unsigned dst, const void* src) {
    asm volatile("cp.async.cg.shared.global [%0], [%1], 16;" :: "r"(dst), "l"(src));
}
__device__ __forceinline__ void cp_commit() {
    asm volatile("cp.async.commit_group;");
}
template<int N>
__device__ __forceinline__ void cp_wait() {
    asm volatile("cp.async.wait_group %0;" :: "n"(N));
}
__device__ __forceinline__ float fexp2(float x) {
    float y;
    asm("ex2.approx.f32 %0, %1;" : "=f"(y) : "f"(x));
    return y;
}
__device__ __forceinline__ void mma_f16(float c[4], const unsigned a[4], const unsigned b[2]) {
    asm volatile("mma.sync.aligned.m16n8k16.row.col.f32.f16.f16.f32 "
        "{%0,%1,%2,%3}, {%4,%5,%6,%7}, {%8,%9}, {%0,%1,%2,%3};"
        : "+f"(c[0]), "+f"(c[1]), "+f"(c[2]), "+f"(c[3])
        : "r"(a[0]), "r"(a[1]), "r"(a[2]), "r"(a[3]), "r"(b[0]), "r"(b[1]));
}
__device__ __forceinline__ void ldsm4(unsigned &r0, unsigned &r1, unsigned &r2, unsigned &r3, unsigned addr) {
    asm volatile("ldmatrix.sync.aligned.m8n8.x4.shared.b16 {%0,%1,%2,%3}, [%4];"
        : "=r"(r0), "=r"(r1), "=r"(r2), "=r"(r3) : "r"(addr));
}
__device__ __forceinline__ void ldsm4t(unsigned &r0, unsigned &r1, unsigned &r2, unsigned &r3, unsigned addr) {
    asm volatile("ldmatrix.sync.aligned.m8n8.x4.trans.shared.b16 {%0,%1,%2,%3}, [%4];"
        : "=r"(r0), "=r"(r1), "=r"(r2), "=r"(r3) : "r"(addr));
}

// ---------------- weight fp32 -> fp16 conversion ----------------
__global__ void wcvt_kernel(const float* __restrict__ wq, const float* __restrict__ wk,
                            const float* __restrict__ wv, const float* __restrict__ wp) {
    int i = blockIdx.x * 256 + threadIdx.x;
    h_w[i          ] = __float2half(wq[i]);
    h_w[i +   CH*CH] = __float2half(wk[i]);
    h_w[i + 2*CH*CH] = __float2half(wv[i]);
    h_w[i + 3*CH*CH] = __float2half(wp[i]);
}

// ---------------- GroupNorm: 3-kernel deterministic split ----------------
__global__ void gn_partial_kernel(const float* __restrict__ x) {
    const int SEG = CPG*NPOS/GSPLIT;            // 16384
    int grp = blockIdx.x / GSPLIT;
    int seg = blockIdx.x % GSPLIT;
    const float4* px = reinterpret_cast<const float4*>(
        x + (size_t)grp*CPG*NPOS + (size_t)seg*SEG);
    int tid = threadIdx.x;
    float s = 0.f, s2 = 0.f;
    #pragma unroll
    for (int i = 0; i < SEG/4/256; i++) {
        float4 t = px[tid + i*256];
        s  += t.x + t.y + t.z + t.w;
        s2 += t.x*t.x + t.y*t.y + t.z*t.z + t.w*t.w;
    }
    __shared__ float rs[32], rs2[32];
    int lane = tid & 31, wid = tid >> 5;
    #pragma unroll
    for (int o = 16; o > 0; o >>= 1) {
        s  += __shfl_xor_sync(0xffffffffu, s,  o);
        s2 += __shfl_xor_sync(0xffffffffu, s2, o);
    }
    if (lane == 0) { rs[wid] = s; rs2[wid] = s2; }
    __syncthreads();
    if (wid == 0) {
        s  = (lane < 8) ? rs[lane]  : 0.f;
        s2 = (lane < 8) ? rs2[lane] : 0.f;
        #pragma unroll
        for (int o = 4; o > 0; o >>= 1) {
            s  += __shfl_xor_sync(0xffffffffu, s,  o);
            s2 += __shfl_xor_sync(0xffffffffu, s2, o);
        }
        if (lane == 0) {
            g_part[blockIdx.x*2    ] = s;
            g_part[blockIdx.x*2 + 1] = s2;
        }
    }
}

__global__ void gn_stats_kernel() {
    int g = threadIdx.x;
    if (g >= BATCH*NGRP) return;
    float s = 0.f, s2 = 0.f;
    #pragma unroll
    for (int i = 0; i < GSPLIT; i++) {
        s  += g_part[(g*GSPLIT + i)*2    ];
        s2 += g_part[(g*GSPLIT + i)*2 + 1];
    }
    const float invN = 1.f / (CPG*NPOS);
    float mean = s * invN;
    float var  = s2 * invN - mean*mean;
    g_stats[g*2    ] = mean;
    g_stats[g*2 + 1] = rsqrtf(var + 1e-5f);
}

__global__ void gn_norm_kernel(const float* __restrict__ x,
                               const float* __restrict__ gamma,
                               const float* __restrict__ beta) {
    size_t base = ((size_t)blockIdx.x*256 + threadIdx.x) * 8;
    int c  = (int)((base / NPOS) & (CH-1));
    int gi = (int)(base / ((size_t)CPG*NPOS));
    float mean = g_stats[gi*2], rstd = g_stats[gi*2+1];
    float ga = gamma[c] * rstd;
    float be = beta[c] - mean * ga;
    const float4* px = reinterpret_cast<const float4*>(x + base);
    float4 a = px[0], b = px[1];
    __half2 h[4];
    h[0] = __floats2half2_rn(a.x*ga+be, a.y*ga+be);
    h[1] = __floats2half2_rn(a.z*ga+be, a.w*ga+be);
    h[2] = __floats2half2_rn(b.x*ga+be, b.y*ga+be);
    h[3] = __floats2half2_rn(b.z*ga+be, b.w*ga+be);
    *reinterpret_cast<uint4*>(&h_xn[base]) = *reinterpret_cast<uint4*>(h);
}

// ---------------- generic batched fp16 tensor-core GEMM (projections) ----------------
template<bool AKM, bool BNM, bool OUTF32>
__global__ __launch_bounds__(256, 2)
void hgemm_kernel(const __half* __restrict__ A, const __half* __restrict__ B,
                  void* __restrict__ Cp,
                  int K, int lda, int ldb, int ldc,
                  long long sA, long long sB, long long sC,
                  float alpha,
                  const float* __restrict__ bias,
                  const float* __restrict__ resid, long long sR)
{
    const int BM = 128, BN = 128;
    constexpr int ASZ = AKM ? 32*136 : 128*40;
    constexpr int BSZ = BNM ? 128*40 : 32*136;
    __shared__ __align__(16) __half As[3][ASZ];
    __shared__ __align__(16) __half Bs[3][BSZ];

    int bz = blockIdx.z;
    A += (size_t)bz * sA;
    B += (size_t)bz * sB;
    int m0 = blockIdx.y * BM;
    int n0 = blockIdx.x * BN;
    int tid = threadIdx.x, lane = tid & 31, warp = tid >> 5;
    int wm = (warp & 1) * 64;
    int wn = (warp >> 1) * 32;

    const __half* aptr[2]; int asmo[2];
    const __half* bptr[2]; int bsmo[2];
    #pragma unroll
    for (int i = 0; i < 2; i++) {
        int idx = tid + i*256;
        if (AKM) { int r = idx >> 4, c = (idx & 15)*8;
                   aptr[i] = A + (size_t)r*lda + m0 + c; asmo[i] = r*136 + c; }
        else     { int r = idx >> 2, c = (idx & 3)*8;
                   aptr[i] = A + (size_t)(m0+r)*lda + c; asmo[i] = r*40 + c; }
        if (BNM) { int r = idx >> 2, c = (idx & 3)*8;
                   bptr[i] = B + (size_t)(n0+r)*ldb + c; bsmo[i] = r*40 + c; }
        else     { int r = idx >> 4, c = (idx & 15)*8;
                   bptr[i] = B + (size_t)r*ldb + n0 + c; bsmo[i] = r*136 + c; }
    }
    const long long stepA = AKM ? (long long)32*lda : 32;
    const long long stepB = BNM ? 32 : (long long)32*ldb;

    unsigned abase = (unsigned)__cvta_generic_to_shared(&As[0][0]);
    unsigned bbase = (unsigned)__cvta_generic_to_shared(&Bs[0][0]);

    #pragma unroll
    for (int st = 0; st < 2; st++) {
        #pragma unroll
        for (int i = 0; i < 2; i++) {
            cp_async16(abase + (st*ASZ + asmo[i])*2u, aptr[i]);
            cp_async16(bbase + (st*BSZ + bsmo[i])*2u, bptr[i]);
            aptr[i] += stepA; bptr[i] += stepB;
        }
        cp_commit();
    }

    float acc[4][4][4] = {};
    int nk = K >> 5;

    for (int s = 0; s < nk; s++) {
        cp_wait<1>();
        __syncthreads();

        if (s + 2 < nk) {
            int st = (s + 2) % 3;
            #pragma unroll
            for (int i = 0; i < 2; i++) {
                cp_async16(abase + (st*ASZ + asmo[i])*2u, aptr[i]);
                cp_async16(bbase + (st*BSZ + bsmo[i])*2u, bptr[i]);
                aptr[i] += stepA; bptr[i] += stepB;
            }
        }
        cp_commit();

        int cur = s % 3;
        unsigned ab = abase + (unsigned)(cur*ASZ)*2u;
        unsigned bb = bbase + (unsigned)(cur*BSZ)*2u;

        #pragma unroll
        for (int ks = 0; ks < 2; ks++) {
            unsigned af[4][4], bf[4][2];
            #pragma unroll
            for (int mi = 0; mi < 4; mi++) {
                unsigned addr;
                if (AKM) {
                    addr = ab + 2u*(((lane&7) + ((lane>>4)&1)*8 + ks*16)*136
                                     + wm + mi*16 + ((lane>>3)&1)*8);
                    ldsm4t(af[mi][0], af[mi][1], af[mi][2], af[mi][3], addr);
                } else {
                    addr = ab + 2u*((wm + mi*16 + (lane&15))*40 + ks*16 + (lane>>4)*8);
                    ldsm4(af[mi][0], af[mi][1], af[mi][2], af[mi][3], addr);
                }
            }
            #pragma unroll
            for (int bi = 0; bi < 2; bi++) {
                unsigned q0, q1, q2, q3, addr;
                if (BNM) {
                    addr = bb + 2u*((wn + bi*16 + (lane&7) + (lane>>4)*8)*40
                                     + ks*16 + ((lane>>3)&1)*8);
                    ldsm4(q0, q1, q2, q3, addr);
                } else {
                    addr = bb + 2u*(((lane&7) + ((lane>>3)&1)*8 + ks*16)*136
                                     + wn + bi*16 + (lane>>4)*8);
                    ldsm4t(q0, q1, q2, q3, addr);
                }
                bf[bi*2  ][0] = q0; bf[bi*2  ][1] = q1;
                bf[bi*2+1][0] = q2; bf[bi*2+1][1] = q3;
            }
            #pragma unroll
            for (int mi = 0; mi < 4; mi++)
                #pragma unroll
                for (int nj = 0; nj < 4; nj++)
                    mma_f16(acc[mi][nj], af[mi], bf[nj]);
        }
    }

    if (OUTF32) {
        float* C = (float*)Cp + (size_t)bz * sC;
        const float* R = resid ? resid + (size_t)bz * sR : nullptr;
        #pragma unroll
        for (int mi = 0; mi < 4; mi++) {
            #pragma unroll
            for (int h = 0; h < 2; h++) {
                int m = m0 + wm + mi*16 + (lane >> 2) + h*8;
                float bv = bias ? bias[m] : 0.f;
                #pragma unroll
                for (int nj = 0; nj < 4; nj++) {
                    int n = n0 + wn + nj*8 + 2*(lane & 3);
                    float2 val;
                    val.x = acc[mi][nj][h*2+0] * alpha + bv;
                    val.y = acc[mi][nj][h*2+1] * alpha + bv;
                    if (R) {
                        val.x += R[(size_t)m*ldc + n];
                        val.y += R[(size_t)m*ldc + n + 1];
                    }
                    *reinterpret_cast<float2*>(&C[(size_t)m*ldc + n]) = val;
                }
            }
        }
    } else {
        __half* C = (__half*)Cp + (size_t)bz * sC;
        #pragma unroll
        for (int mi = 0; mi < 4; mi++) {
            #pragma unroll
            for (int h = 0; h < 2; h++) {
                int m = m0 + wm + mi*16 + (lane >> 2) + h*8;
                float bv = bias ? bias[m] : 0.f;
                #pragma unroll
                for (int nj = 0; nj < 4; nj++) {
                    int n = n0 + wn + nj*8 + 2*(lane & 3);
                    __half2 hv = __floats2half2_rn(acc[mi][nj][h*2+0]*alpha + bv,
                                                   acc[mi][nj][h*2+1]*alpha + bv);
                    *reinterpret_cast<__half2*>(&C[(size_t)m*ldc + n]) = hv;
                }
            }
        }
    }
}

// ---------------- fused flash attention ----------------
// grid (NPOS/BR, BATCH), 256 threads (8 warps), 1 CTA/SM.
// Q/K/V stored [b][c][i] fp16. Output h_o stored [b][i][c] fp16 (for BNM proj).
// Each warp owns 16 Q-rows x full C=256. Online softmax, O accum in mma C frags.
#define QS_OFF  0
#define QS_LD   136
#define KS_OFF  34816              // 256*136
#define KS_LD   72
#define KS_SZ   (256*72)           // 18432 halves
#define VS_OFF  (KS_OFF + 2*KS_SZ)
#define VS_SZ   KS_SZ
#define FLASH_SMEM ((KS_OFF + 2*KS_SZ + 2*VS_SZ)*2)   // 217088 bytes
#define OS_LD   264

__global__ __launch_bounds__(256, 1)
void flash_kernel(const __half* __restrict__ Q, const __half* __restrict__ Kg,
                  const __half* __restrict__ Vg, __half* __restrict__ Og)
{
    extern __shared__ __half smem[];
    int b  = blockIdx.y;
    int i0 = blockIdx.x * BR;
    const size_t sX = (size_t)CH * NPOS;
    Q  += (size_t)b*sX; Kg += (size_t)b*sX; Vg += (size_t)b*sX;

    int tid = threadIdx.x, lane = tid & 31, warp = tid >> 5;
    unsigned sbase = (unsigned)__cvta_generic_to_shared(smem);

    // prologue: Q tile + K/V stage 0 (group 0), K/V stage 1 (group 1)
    #pragma unroll
    for (int i = 0; i < 16; i++) {
        int idx = tid + i*256;
        int c = idx >> 4, col = (idx & 15)*8;
        cp_async16(sbase + (unsigned)(QS_OFF + c*QS_LD + col)*2u,
                   Q + (size_t)c*NPOS + i0 + col);
    }
    #pragma unroll
    for (int i = 0; i < 8; i++) {
        int idx = tid + i*256;
        int c = idx >> 3, col = (idx & 7)*8;
        cp_async16(sbase + (unsigned)(KS_OFF + c*KS_LD + col)*2u,
                   Kg + (size_t)c*NPOS + col);
        cp_async16(sbase + (unsigned)(VS_OFF + c*KS_LD + col)*2u,
                   Vg + (size_t)c*NPOS + col);
    }
    cp_commit();
    #pragma unroll
    for (int i = 0; i < 8; i++) {
        int idx = tid + i*256;
        int c = idx >> 3, col = (idx & 7)*8;
        cp_async16(sbase + (unsigned)(KS_OFF + KS_SZ + c*KS_LD + col)*2u,
                   Kg + (size_t)c*NPOS + BC + col);
        cp_async16(sbase + (unsigned)(VS_OFF + VS_SZ + c*KS_LD + col)*2u,
                   Vg + (size_t)c*NPOS + BC + col);
    }
    cp_commit();

    float oacc[32][4] = {};        // 32 c-tiles (8 wide) of 16-row warp band
    float m0 = -CUDART_INF_F, m1 = -CUDART_INF_F;
    float l0 = 0.f, l1 = 0.f;

    const int NITER = NPOS / BC;   // 64
    for (int s = 0; s < NITER; s++) {
        cp_wait<1>();
        __syncthreads();
        int cur = s & 1;
        unsigned qb = sbase;
        unsigned kb = sbase + (unsigned)(KS_OFF + cur*KS_SZ)*2u;
        unsigned vb = sbase + (unsigned)(VS_OFF + cur*VS_SZ)*2u;

        // ---- S(16x64) = Q_warp^T K_tile, K-dim = C = 256
        float sacc[8][4] = {};
        #pragma unroll
        for (int ks = 0; ks < 16; ks++) {
            unsigned af[4];
            unsigned aaddr = qb + 2u*(((lane&7) + ((lane>>4)&1)*8 + ks*16)*QS_LD
                                       + warp*16 + ((lane>>3)&1)*8);
            ldsm4t(af[0], af[1], af[2], af[3], aaddr);
            #pragma unroll
            for (int bi = 0; bi < 4; bi++) {
                unsigned q0, q1, q2, q3;
                unsigned baddr = kb + 2u*(((lane&7) + ((lane>>3)&1)*8 + ks*16)*KS_LD
                                           + bi*16 + (lane>>4)*8);
                ldsm4t(q0, q1, q2, q3, baddr);
                unsigned bf0[2] = {q0, q1}, bf1[2] = {q2, q3};
                mma_f16(sacc[bi*2],   af, bf0);
                mma_f16(sacc[bi*2+1], af, bf1);
            }
        }

        // ---- online softmax (rows g = lane>>2 and g+8; quad = lane&3)
        float rmax0 = -CUDART_INF_F, rmax1 = -CUDART_INF_F;
        #pragma unroll
        for (int nt = 0; nt < 8; nt++) {
            rmax0 = fmaxf(rmax0, fmaxf(sacc[nt][0], sacc[nt][1]));
            rmax1 = fmaxf(rmax1, fmaxf(sacc[nt][2], sacc[nt][3]));
        }
        rmax0 = fmaxf(rmax0, __shfl_xor_sync(0xffffffffu, rmax0, 1));
        rmax0 = fmaxf(rmax0, __shfl_xor_sync(0xffffffffu, rmax0, 2));
        rmax1 = fmaxf(rmax1, __shfl_xor_sync(0xffffffffu, rmax1, 1));
        rmax1 = fmaxf(rmax1, __shfl_xor_sync(0xffffffffu, rmax1, 2));
        float mn0 = fmaxf(m0, rmax0 * SCALE_LOG2);
        float mn1 = fmaxf(m1, rmax1 * SCALE_LOG2);
        float corr0 = fexp2(m0 - mn0);
        float corr1 = fexp2(m1 - mn1);
        m0 = mn0; m1 = mn1;

        float rs0 = 0.f, rs1 = 0.f;
        unsigned pa[4][4];
        #pragma unroll
        for (int kt = 0; kt < 4; kt++) {
            float e00 = fexp2(sacc[2*kt  ][0]*SCALE_LOG2 - mn0);
            float e01 = fexp2(sacc[2*kt  ][1]*SCALE_LOG2 - mn0);
            float e02 = fexp2(sacc[2*kt  ][2]*SCALE_LOG2 - mn1);
            float e03 = fexp2(sacc[2*kt  ][3]*SCALE_LOG2 - mn1);
            float e10 = fexp2(sacc[2*kt+1][0]*SCALE_LOG2 - mn0);
            float e11 = fexp2(sacc[2*kt+1][1]*SCALE_LOG2 - mn0);
            float e12 = fexp2(sacc[2*kt+1][2]*SCALE_LOG2 - mn1);
            float e13 = fexp2(sacc[2*kt+1][3]*SCALE_LOG2 - mn1);
            rs0 += e00 + e01 + e10 + e11;
            rs1 += e02 + e03 + e12 + e13;
            __half2 h;
            h = __floats2half2_rn(e00, e01); pa[kt][0] = *(unsigned*)&h;
            h = __floats2half2_rn(e02, e03); pa[kt][1] = *(unsigned*)&h;
            h = __floats2half2_rn(e10, e11); pa[kt][2] = *(unsigned*)&h;
            h = __floats2half2_rn(e12, e13); pa[kt][3] = *(unsigned*)&h;
        }
        rs0 += __shfl_xor_sync(0xffffffffu, rs0, 1);
        rs0 += __shfl_xor_sync(0xffffffffu, rs0, 2);
        rs1 += __shfl_xor_sync(0xffffffffu, rs1, 1);
        rs1 += __shfl_xor_sync(0xffffffffu, rs1, 2);
        l0 = l0*corr0 + rs0;
        l1 = l1*corr1 + rs1;
        #pragma unroll
        for (int nt = 0; nt < 32; nt++) {
            oacc[nt][0] *= corr0; oacc[nt][1] *= corr0;
            oacc[nt][2] *= corr1; oacc[nt][3] *= corr1;
        }

        // ---- O(16x256) += P(16x64) V^T  (B from Vs[c][j], n-major)
        #pragma unroll
        for (int kt = 0; kt < 4; kt++) {
            #pragma unroll
            for (int bi = 0; bi < 16; bi++) {
                unsigned q0, q1, q2, q3;
                unsigned baddr = vb + 2u*((bi*16 + (lane&7) + (lane>>4)*8)*KS_LD
                                           + kt*16 + ((lane>>3)&1)*8);
                ldsm4(q0, q1, q2, q3, baddr);
                unsigned bf0[2] = {q0, q1}, bf1[2] = {q2, q3};
                mma_f16(oacc[bi*2],   pa[kt], bf0);
                mma_f16(oacc[bi*2+1], pa[kt], bf1);
            }
        }

        __syncthreads();
        // prefetch stage s+2 into buffer s&1 (just finished reading)
        if (s + 2 < NITER) {
            int st = s & 1;
            int j0 = (s + 2) * BC;
            #pragma unroll
            for (int i = 0; i < 8; i++) {
                int idx = tid + i*256;
                int c = idx >> 3, col = (idx & 7)*8;
                cp_async16(sbase + (unsigned)(KS_OFF + st*KS_SZ + c*KS_LD + col)*2u,
                           Kg + (size_t)c*NPOS + j0 + col);
                cp_async16(sbase + (unsigned)(VS_OFF + st*VS_SZ + c*KS_LD + col)*2u,
                           Vg + (size_t)c*NPOS + j0 + col);
            }
        }
        cp_commit();
    }

    // ---- epilogue: normalize, stage [i][c] in SMEM (reuse Q region), coalesced store
    float inv0 = 1.f / l0, inv1 = 1.f / l1;
    int g = lane >> 2, t = lane & 3;
    #pragma unroll
    for (int nt = 0; nt < 32; nt++) {
        int c = nt*8 + 2*t;
        __half2 h0 = __floats2half2_rn(oacc[nt][0]*inv0, oacc[nt][1]*inv0);
        __half2 h1 = __floats2half2_rn(oacc[nt][2]*inv1, oacc[nt][3]*inv1);
        *reinterpret_cast<__half2*>(&smem[(warp*16 + g    )*OS_LD + c]) = h0;
        *reinterpret_cast<__half2*>(&smem[(warp*16 + g + 8)*OS_LD + c]) = h1;
    }
    __syncthreads();
    __half* Ob = Og + (size_t)b*sX + (size_t)i0*CH;
    #pragma unroll
    for (int i = 0; i < 16; i++) {
        int idx = tid + i*256;
        int row = idx >> 5, col = (idx & 31)*8;
        *reinterpret_cast<uint4*>(&Ob[(size_t)row*CH + col]) =
            *reinterpret_cast<uint4*>(&smem[row*OS_LD + col]);
    }
}

// ---------------- launcher ----------------
extern "C" void kernel_launch(void* const* d_in, const int* in_sizes, int n_in,
                              void* d_out, int out_size) {
    const float* x     = (const float*)d_in[0];
    const float* gamma = (const float*)d_in[1];
    const float* beta  = (const float*)d_in[2];
    const float* wq    = (const float*)d_in[3];
    const float* bq    = (const float*)d_in[4];
    const float* wk    = (const float*)d_in[5];
    const float* bk    = (const float*)d_in[6];
    const float* wv    = (const float*)d_in[7];
    const float* bv    = (const float*)d_in[8];
    const float* wp    = (const float*)d_in[9];
    const float* bp    = (const float*)d_in[10];
    float* out = (float*)d_out;

    __half *xn, *q, *k, *v, *o, *w;
    cudaGetSymbolAddress((void**)&xn, h_xn);
    cudaGetSymbolAddress((void**)&q,  h_q);
    cudaGetSymbolAddress((void**)&k,  h_k);
    cudaGetSymbolAddress((void**)&v,  h_v);
    cudaGetSymbolAddress((void**)&o,  h_o);
    cudaGetSymbolAddress((void**)&w,  h_w);

    static bool attr_set = false;
    if (!attr_set) {
        cudaFuncSetAttribute(flash_kernel,
                             cudaFuncAttributeMaxDynamicSharedMemorySize, FLASH_SMEM);
        attr_set = true;
    }

    // 0. weights fp32 -> fp16
    wcvt_kernel<<<CH*CH/256, 256>>>(wq, wk, wv, wp);

    // 1. GroupNorm -> fp16 xn
    gn_partial_kernel<<<BATCH*NGRP*GSPLIT, 256>>>(x);
    gn_stats_kernel<<<1, 64>>>();
    gn_norm_kernel<<<(BATCH*CH*NPOS)/(256*8), 256>>>(x, gamma, beta);

    const long long sX = (long long)CH * NPOS;

    // 2. Q/K/V projections: W[256,256] x Xn[256,4096] -> fp16 [c][i]
    dim3 gq(NPOS/128, CH/128, BATCH);
    hgemm_kernel<false,false,false><<<gq,256>>>(w,           xn, q, CH, CH, NPOS, NPOS,
                                                0, sX, sX, 1.f, bq, nullptr, 0);
    hgemm_kernel<false,false,false><<<gq,256>>>(w +   CH*CH, xn, k, CH, CH, NPOS, NPOS,
                                                0, sX, sX, 1.f, bk, nullptr, 0);
    hgemm_kernel<false,false,false><<<gq,256>>>(w + 2*CH*CH, xn, v, CH, CH, NPOS, NPOS,
                                                0, sX, sX, 1.f, bv, nullptr, 0);

    // 3-5. fused flash attention -> o [i][c]
    dim3 gf(NPOS/BR, BATCH);
    flash_kernel<<<gf, 256, FLASH_SMEM>>>(q, k, v, o);

    // 6. out = Wp*O + bp + x (residual, fp32 out); O is n-major (BNM)
    hgemm_kernel<false,true,true><<<gq,256>>>(w + 3*CH*CH, o, out, CH, CH, CH, NPOS,
                                              0, sX, sX, 1.f, bp, x, sX);
}

// round 17
// speedup vs baseline: 10.6046x; 1.0006x over previous
#include <cuda_runtime.h>
#include <cuda_fp16.h>
#include <math_constants.h>

#define BATCH 8
#define CH    256
#define NPOS  4096      // 64*64
#define NGRP  8
#define CPG   (CH/NGRP) // 32
#define GSPLIT 8

#define BR 128
#define BC 64
// softmax scale folded into log2 domain: (1/16) * log2(e)
#define SCALE_LOG2 0.09016844f

// ---------------- scratch (device globals; no allocation allowed) ----------------
__device__ __align__(16) __half h_xn [(size_t)BATCH*CH*NPOS];
__device__ __align__(16) __half h_q  [(size_t)BATCH*CH*NPOS];
__device__ __align__(16) __half h_k  [(size_t)BATCH*CH*NPOS];
__device__ __align__(16) __half h_v  [(size_t)BATCH*CH*NPOS];
__device__ __align__(16) __half h_o  [(size_t)BATCH*CH*NPOS];   // [b][i][c] layout!
__device__ __align__(16) __half h_w  [4*(size_t)CH*CH];
__device__ float g_part [BATCH*NGRP*GSPLIT*2];
__device__ float g_stats[BATCH*NGRP*2];

// ---------------- small helpers ----------------
__device__ __forceinline__ void cp_async16(unsigned dst, const void* src) {
    asm volatile("cp.async.cg.shared.global [%0], [%1], 16;" :: "r"(dst), "l"(src));
}
__device__ __forceinline__ void cp_commit() {
    asm volatile("cp.async.commit_group;");
}
template<int N>
__device__ __forceinline__ void cp_wait() {
    asm volatile("cp.async.wait_group %0;" :: "n"(N));
}
__device__ __forceinline__ float fexp2(float x) {
    float y;
    asm("ex2.approx.f32 %0, %1;" : "=f"(y) : "f"(x));
    return y;
}
__device__ __forceinline__ void mma_f16(float c[4], const unsigned a[4], const unsigned b[2]) {
    asm volatile("mma.sync.aligned.m16n8k16.row.col.f32.f16.f16.f32 "
        "{%0,%1,%2,%3}, {%4,%5,%6,%7}, {%8,%9}, {%0,%1,%2,%3};"
        : "+f"(c[0]), "+f"(c[1]), "+f"(c[2]), "+f"(c[3])
        : "r"(a[0]), "r"(a[1]), "r"(a[2]), "r"(a[3]), "r"(b[0]), "r"(b[1]));
}
__device__ __forceinline__ void ldsm4(unsigned &r0, unsigned &r1, unsigned &r2, unsigned &r3, unsigned addr) {
    asm volatile("ldmatrix.sync.aligned.m8n8.x4.shared.b16 {%0,%1,%2,%3}, [%4];"
        : "=r"(r0), "=r"(r1), "=r"(r2), "=r"(r3) : "r"(addr));
}
__device__ __forceinline__ void ldsm4t(unsigned &r0, unsigned &r1, unsigned &r2, unsigned &r3, unsigned addr) {
    asm volatile("ldmatrix.sync.aligned.m8n8.x4.trans.shared.b16 {%0,%1,%2,%3}, [%4];"
        : "=r"(r0), "=r"(r1), "=r"(r2), "=r"(r3) : "r"(addr));
}

// ---------------- weight fp32 -> fp16 conversion ----------------
__global__ void wcvt_kernel(const float* __restrict__ wq, const float* __restrict__ wk,
                            const float* __restrict__ wv, const float* __restrict__ wp) {
    int i = blockIdx.x * 256 + threadIdx.x;
    h_w[i          ] = __float2half(wq[i]);
    h_w[i +   CH*CH] = __float2half(wk[i]);
    h_w[i + 2*CH*CH] = __float2half(wv[i]);
    h_w[i + 3*CH*CH] = __float2half(wp[i]);
}

// ---------------- GroupNorm: 3-kernel deterministic split ----------------
__global__ void gn_partial_kernel(const float* __restrict__ x) {
    const int SEG = CPG*NPOS/GSPLIT;            // 16384
    int grp = blockIdx.x / GSPLIT;
    int seg = blockIdx.x % GSPLIT;
    const float4* px = reinterpret_cast<const float4*>(
        x + (size_t)grp*CPG*NPOS + (size_t)seg*SEG);
    int tid = threadIdx.x;
    float s = 0.f, s2 = 0.f;
    #pragma unroll
    for (int i = 0; i < SEG/4/256; i++) {
        float4 t = px[tid + i*256];
        s  += t.x + t.y + t.z + t.w;
        s2 += t.x*t.x + t.y*t.y + t.z*t.z + t.w*t.w;
    }
    __shared__ float rs[32], rs2[32];
    int lane = tid & 31, wid = tid >> 5;
    #pragma unroll
    for (int o = 16; o > 0; o >>= 1) {
        s  += __shfl_xor_sync(0xffffffffu, s,  o);
        s2 += __shfl_xor_sync(0xffffffffu, s2, o);
    }
    if (lane == 0) { rs[wid] = s; rs2[wid] = s2; }
    __syncthreads();
    if (wid == 0) {
        s  = (lane < 8) ? rs[lane]  : 0.f;
        s2 = (lane < 8) ? rs2[lane] : 0.f;
        #pragma unroll
        for (int o = 4; o > 0; o >>= 1) {
            s  += __shfl_xor_sync(0xffffffffu, s,  o);
            s2 += __shfl_xor_sync(0xffffffffu, s2, o);
        }
        if (lane == 0) {
            g_part[blockIdx.x*2    ] = s;
            g_part[blockIdx.x*2 + 1] = s2;
        }
    }
}

__global__ void gn_stats_kernel() {
    int g = threadIdx.x;
    if (g >= BATCH*NGRP) return;
    float s = 0.f, s2 = 0.f;
    #pragma unroll
    for (int i = 0; i < GSPLIT; i++) {
        s  += g_part[(g*GSPLIT + i)*2    ];
        s2 += g_part[(g*GSPLIT + i)*2 + 1];
    }
    const float invN = 1.f / (CPG*NPOS);
    float mean = s * invN;
    float var  = s2 * invN - mean*mean;
    g_stats[g*2    ] = mean;
    g_stats[g*2 + 1] = rsqrtf(var + 1e-5f);
}

__global__ void gn_norm_kernel(const float* __restrict__ x,
                               const float* __restrict__ gamma,
                               const float* __restrict__ beta) {
    size_t base = ((size_t)blockIdx.x*256 + threadIdx.x) * 8;
    int c  = (int)((base / NPOS) & (CH-1));
    int gi = (int)(base / ((size_t)CPG*NPOS));
    float mean = g_stats[gi*2], rstd = g_stats[gi*2+1];
    float ga = gamma[c] * rstd;
    float be = beta[c] - mean * ga;
    const float4* px = reinterpret_cast<const float4*>(x + base);
    float4 a = px[0], b = px[1];
    __half2 h[4];
    h[0] = __floats2half2_rn(a.x*ga+be, a.y*ga+be);
    h[1] = __floats2half2_rn(a.z*ga+be, a.w*ga+be);
    h[2] = __floats2half2_rn(b.x*ga+be, b.y*ga+be);
    h[3] = __floats2half2_rn(b.z*ga+be, b.w*ga+be);
    *reinterpret_cast<uint4*>(&h_xn[base]) = *reinterpret_cast<uint4*>(h);
}

// ---------------- generic batched fp16 tensor-core GEMM (projections) ----------------
template<bool AKM, bool BNM, bool OUTF32>
__global__ __launch_bounds__(256, 2)
void hgemm_kernel(const __half* __restrict__ A, const __half* __restrict__ B,
                  void* __restrict__ Cp,
                  int K, int lda, int ldb, int ldc,
                  long long sA, long long sB, long long sC,
                  float alpha,
                  const float* __restrict__ bias,
                  const float* __restrict__ resid, long long sR)
{
    const int BM = 128, BN = 128;
    constexpr int ASZ = AKM ? 32*136 : 128*40;
    constexpr int BSZ = BNM ? 128*40 : 32*136;
    __shared__ __align__(16) __half As[3][ASZ];
    __shared__ __align__(16) __half Bs[3][BSZ];

    int bz = blockIdx.z;
    A += (size_t)bz * sA;
    B += (size_t)bz * sB;
    int m0 = blockIdx.y * BM;
    int n0 = blockIdx.x * BN;
    int tid = threadIdx.x, lane = tid & 31, warp = tid >> 5;
    int wm = (warp & 1) * 64;
    int wn = (warp >> 1) * 32;

    const __half* aptr[2]; int asmo[2];
    const __half* bptr[2]; int bsmo[2];
    #pragma unroll
    for (int i = 0; i < 2; i++) {
        int idx = tid + i*256;
        if (AKM) { int r = idx >> 4, c = (idx & 15)*8;
                   aptr[i] = A + (size_t)r*lda + m0 + c; asmo[i] = r*136 + c; }
        else     { int r = idx >> 2, c = (idx & 3)*8;
                   aptr[i] = A + (size_t)(m0+r)*lda + c; asmo[i] = r*40 + c; }
        if (BNM) { int r = idx >> 2, c = (idx & 3)*8;
                   bptr[i] = B + (size_t)(n0+r)*ldb + c; bsmo[i] = r*40 + c; }
        else     { int r = idx >> 4, c = (idx & 15)*8;
                   bptr[i] = B + (size_t)r*ldb + n0 + c; bsmo[i] = r*136 + c; }
    }
    const long long stepA = AKM ? (long long)32*lda : 32;
    const long long stepB = BNM ? 32 : (long long)32*ldb;

    unsigned abase = (unsigned)__cvta_generic_to_shared(&As[0][0]);
    unsigned bbase = (unsigned)__cvta_generic_to_shared(&Bs[0][0]);

    #pragma unroll
    for (int st = 0; st < 2; st++) {
        #pragma unroll
        for (int i = 0; i < 2; i++) {
            cp_async16(abase + (st*ASZ + asmo[i])*2u, aptr[i]);
            cp_async16(bbase + (st*BSZ + bsmo[i])*2u, bptr[i]);
            aptr[i] += stepA; bptr[i] += stepB;
        }
        cp_commit();
    }

    float acc[4][4][4] = {};
    int nk = K >> 5;

    for (int s = 0; s < nk; s++) {
        cp_wait<1>();
        __syncthreads();

        if (s + 2 < nk) {
            int st = (s + 2) % 3;
            #pragma unroll
            for (int i = 0; i < 2; i++) {
                cp_async16(abase + (st*ASZ + asmo[i])*2u, aptr[i]);
                cp_async16(bbase + (st*BSZ + bsmo[i])*2u, bptr[i]);
                aptr[i] += stepA; bptr[i] += stepB;
            }
        }
        cp_commit();

        int cur = s % 3;
        unsigned ab = abase + (unsigned)(cur*ASZ)*2u;
        unsigned bb = bbase + (unsigned)(cur*BSZ)*2u;

        #pragma unroll
        for (int ks = 0; ks < 2; ks++) {
            unsigned af[4][4], bf[4][2];
            #pragma unroll
            for (int mi = 0; mi < 4; mi++) {
                unsigned addr;
                if (AKM) {
                    addr = ab + 2u*(((lane&7) + ((lane>>4)&1)*8 + ks*16)*136
                                     + wm + mi*16 + ((lane>>3)&1)*8);
                    ldsm4t(af[mi][0], af[mi][1], af[mi][2], af[mi][3], addr);
                } else {
                    addr = ab + 2u*((wm + mi*16 + (lane&15))*40 + ks*16 + (lane>>4)*8);
                    ldsm4(af[mi][0], af[mi][1], af[mi][2], af[mi][3], addr);
                }
            }
            #pragma unroll
            for (int bi = 0; bi < 2; bi++) {
                unsigned q0, q1, q2, q3, addr;
                if (BNM) {
                    addr = bb + 2u*((wn + bi*16 + (lane&7) + (lane>>4)*8)*40
                                     + ks*16 + ((lane>>3)&1)*8);
                    ldsm4(q0, q1, q2, q3, addr);
                } else {
                    addr = bb + 2u*(((lane&7) + ((lane>>3)&1)*8 + ks*16)*136
                                     + wn + bi*16 + (lane>>4)*8);
                    ldsm4t(q0, q1, q2, q3, addr);
                }
                bf[bi*2  ][0] = q0; bf[bi*2  ][1] = q1;
                bf[bi*2+1][0] = q2; bf[bi*2+1][1] = q3;
            }
            #pragma unroll
            for (int mi = 0; mi < 4; mi++)
                #pragma unroll
                for (int nj = 0; nj < 4; nj++)
                    mma_f16(acc[mi][nj], af[mi], bf[nj]);
        }
    }

    if (OUTF32) {
        float* C = (float*)Cp + (size_t)bz * sC;
        const float* R = resid ? resid + (size_t)bz * sR : nullptr;
        #pragma unroll
        for (int mi = 0; mi < 4; mi++) {
            #pragma unroll
            for (int h = 0; h < 2; h++) {
                int m = m0 + wm + mi*16 + (lane >> 2) + h*8;
                float bv = bias ? bias[m] : 0.f;
                #pragma unroll
                for (int nj = 0; nj < 4; nj++) {
                    int n = n0 + wn + nj*8 + 2*(lane & 3);
                    float2 val;
                    val.x = acc[mi][nj][h*2+0] * alpha + bv;
                    val.y = acc[mi][nj][h*2+1] * alpha + bv;
                    if (R) {
                        val.x += R[(size_t)m*ldc + n];
                        val.y += R[(size_t)m*ldc + n + 1];
                    }
                    *reinterpret_cast<float2*>(&C[(size_t)m*ldc + n]) = val;
                }
            }
        }
    } else {
        __half* C = (__half*)Cp + (size_t)bz * sC;
        #pragma unroll
        for (int mi = 0; mi < 4; mi++) {
            #pragma unroll
            for (int h = 0; h < 2; h++) {
                int m = m0 + wm + mi*16 + (lane >> 2) + h*8;
                float bv = bias ? bias[m] : 0.f;
                #pragma unroll
                for (int nj = 0; nj < 4; nj++) {
                    int n = n0 + wn + nj*8 + 2*(lane & 3);
                    __half2 hv = __floats2half2_rn(acc[mi][nj][h*2+0]*alpha + bv,
                                                   acc[mi][nj][h*2+1]*alpha + bv);
                    *reinterpret_cast<__half2*>(&C[(size_t)m*ldc + n]) = hv;
                }
            }
        }
    }
}

// ---------------- fused flash attention ----------------
// grid (NPOS/BR, BATCH), 256 threads (8 warps), 1 CTA/SM.
// Q/K/V stored [b][c][i] fp16. Output h_o stored [b][i][c] fp16 (for BNM proj).
// Each warp owns 16 Q-rows x full C=256. Online softmax, O accum in mma C frags.
#define QS_OFF  0
#define QS_LD   136
#define KS_OFF  34816              // 256*136
#define KS_LD   72
#define KS_SZ   (256*72)           // 18432 halves
#define VS_OFF  (KS_OFF + 2*KS_SZ)
#define VS_SZ   KS_SZ
#define FLASH_SMEM ((KS_OFF + 2*KS_SZ + 2*VS_SZ)*2)   // 217088 bytes
#define OS_LD   264

__global__ __launch_bounds__(256, 1)
void flash_kernel(const __half* __restrict__ Q, const __half* __restrict__ Kg,
                  const __half* __restrict__ Vg, __half* __restrict__ Og)
{
    extern __shared__ __half smem[];
    int b  = blockIdx.y;
    int i0 = blockIdx.x * BR;
    const size_t sX = (size_t)CH * NPOS;
    Q  += (size_t)b*sX; Kg += (size_t)b*sX; Vg += (size_t)b*sX;

    int tid = threadIdx.x, lane = tid & 31, warp = tid >> 5;
    unsigned sbase = (unsigned)__cvta_generic_to_shared(smem);

    // prologue: Q tile + K/V stage 0 (group 0), K/V stage 1 (group 1)
    #pragma unroll
    for (int i = 0; i < 16; i++) {
        int idx = tid + i*256;
        int c = idx >> 4, col = (idx & 15)*8;
        cp_async16(sbase + (unsigned)(QS_OFF + c*QS_LD + col)*2u,
                   Q + (size_t)c*NPOS + i0 + col);
    }
    #pragma unroll
    for (int i = 0; i < 8; i++) {
        int idx = tid + i*256;
        int c = idx >> 3, col = (idx & 7)*8;
        cp_async16(sbase + (unsigned)(KS_OFF + c*KS_LD + col)*2u,
                   Kg + (size_t)c*NPOS + col);
        cp_async16(sbase + (unsigned)(VS_OFF + c*KS_LD + col)*2u,
                   Vg + (size_t)c*NPOS + col);
    }
    cp_commit();
    #pragma unroll
    for (int i = 0; i < 8; i++) {
        int idx = tid + i*256;
        int c = idx >> 3, col = (idx & 7)*8;
        cp_async16(sbase + (unsigned)(KS_OFF + KS_SZ + c*KS_LD + col)*2u,
                   Kg + (size_t)c*NPOS + BC + col);
        cp_async16(sbase + (unsigned)(VS_OFF + VS_SZ + c*KS_LD + col)*2u,
                   Vg + (size_t)c*NPOS + BC + col);
    }
    cp_commit();

    float oacc[32][4] = {};        // 32 c-tiles (8 wide) of 16-row warp band
    float m0 = -CUDART_INF_F, m1 = -CUDART_INF_F;
    float l0 = 0.f, l1 = 0.f;

    const int NITER = NPOS / BC;   // 64
    for (int s = 0; s < NITER; s++) {
        cp_wait<1>();
        __syncthreads();
        int cur = s & 1;
        unsigned qb = sbase;
        unsigned kb = sbase + (unsigned)(KS_OFF + cur*KS_SZ)*2u;
        unsigned vb = sbase + (unsigned)(VS_OFF + cur*VS_SZ)*2u;

        // ---- S(16x64) = Q_warp^T K_tile, K-dim = C = 256
        float sacc[8][4] = {};
        #pragma unroll
        for (int ks = 0; ks < 16; ks++) {
            unsigned af[4];
            unsigned aaddr = qb + 2u*(((lane&7) + ((lane>>4)&1)*8 + ks*16)*QS_LD
                                       + warp*16 + ((lane>>3)&1)*8);
            ldsm4t(af[0], af[1], af[2], af[3], aaddr);
            #pragma unroll
            for (int bi = 0; bi < 4; bi++) {
                unsigned q0, q1, q2, q3;
                unsigned baddr = kb + 2u*(((lane&7) + ((lane>>3)&1)*8 + ks*16)*KS_LD
                                           + bi*16 + (lane>>4)*8);
                ldsm4t(q0, q1, q2, q3, baddr);
                unsigned bf0[2] = {q0, q1}, bf1[2] = {q2, q3};
                mma_f16(sacc[bi*2],   af, bf0);
                mma_f16(sacc[bi*2+1], af, bf1);
            }
        }

        // ---- online softmax (rows g = lane>>2 and g+8; quad = lane&3)
        float rmax0 = -CUDART_INF_F, rmax1 = -CUDART_INF_F;
        #pragma unroll
        for (int nt = 0; nt < 8; nt++) {
            rmax0 = fmaxf(rmax0, fmaxf(sacc[nt][0], sacc[nt][1]));
            rmax1 = fmaxf(rmax1, fmaxf(sacc[nt][2], sacc[nt][3]));
        }
        rmax0 = fmaxf(rmax0, __shfl_xor_sync(0xffffffffu, rmax0, 1));
        rmax0 = fmaxf(rmax0, __shfl_xor_sync(0xffffffffu, rmax0, 2));
        rmax1 = fmaxf(rmax1, __shfl_xor_sync(0xffffffffu, rmax1, 1));
        rmax1 = fmaxf(rmax1, __shfl_xor_sync(0xffffffffu, rmax1, 2));
        float mn0 = fmaxf(m0, rmax0 * SCALE_LOG2);
        float mn1 = fmaxf(m1, rmax1 * SCALE_LOG2);
        float corr0 = fexp2(m0 - mn0);
        float corr1 = fexp2(m1 - mn1);
        m0 = mn0; m1 = mn1;

        float rs0 = 0.f, rs1 = 0.f;
        unsigned pa[4][4];
        #pragma unroll
        for (int kt = 0; kt < 4; kt++) {
            float e00 = fexp2(sacc[2*kt  ][0]*SCALE_LOG2 - mn0);
            float e01 = fexp2(sacc[2*kt  ][1]*SCALE_LOG2 - mn0);
            float e02 = fexp2(sacc[2*kt  ][2]*SCALE_LOG2 - mn1);
            float e03 = fexp2(sacc[2*kt  ][3]*SCALE_LOG2 - mn1);
            float e10 = fexp2(sacc[2*kt+1][0]*SCALE_LOG2 - mn0);
            float e11 = fexp2(sacc[2*kt+1][1]*SCALE_LOG2 - mn0);
            float e12 = fexp2(sacc[2*kt+1][2]*SCALE_LOG2 - mn1);
            float e13 = fexp2(sacc[2*kt+1][3]*SCALE_LOG2 - mn1);
            rs0 += e00 + e01 + e10 + e11;
            rs1 += e02 + e03 + e12 + e13;
            __half2 h;
            h = __floats2half2_rn(e00, e01); pa[kt][0] = *(unsigned*)&h;
            h = __floats2half2_rn(e02, e03); pa[kt][1] = *(unsigned*)&h;
            h = __floats2half2_rn(e10, e11); pa[kt][2] = *(unsigned*)&h;
            h = __floats2half2_rn(e12, e13); pa[kt][3] = *(unsigned*)&h;
        }
        rs0 += __shfl_xor_sync(0xffffffffu, rs0, 1);
        rs0 += __shfl_xor_sync(0xffffffffu, rs0, 2);
        rs1 += __shfl_xor_sync(0xffffffffu, rs1, 1);
        rs1 += __shfl_xor_sync(0xffffffffu, rs1, 2);
        l0 = l0*corr0 + rs0;
        l1 = l1*corr1 + rs1;
        #pragma unroll
        for (int nt = 0; nt < 32; nt++) {
            oacc[nt][0] *= corr0; oacc[nt][1] *= corr0;
            oacc[nt][2] *= corr1; oacc[nt][3] *= corr1;
        }

        // ---- O(16x256) += P(16x64) V^T  (B from Vs[c][j], n-major)
        #pragma unroll
        for (int kt = 0; kt < 4; kt++) {
            #pragma unroll
            for (int bi = 0; bi < 16; bi++) {
                unsigned q0, q1, q2, q3;
                unsigned baddr = vb + 2u*((bi*16 + (lane&7) + (lane>>4)*8)*KS_LD
                                           + kt*16 + ((lane>>3)&1)*8);
                ldsm4(q0, q1, q2, q3, baddr);
                unsigned bf0[2] = {q0, q1}, bf1[2] = {q2, q3};
                mma_f16(oacc[bi*2],   pa[kt], bf0);
                mma_f16(oacc[bi*2+1], pa[kt], bf1);
            }
        }

        __syncthreads();
        // prefetch stage s+2 into buffer s&1 (just finished reading)
        if (s + 2 < NITER) {
            int st = s & 1;
            int j0 = (s + 2) * BC;
            #pragma unroll
            for (int i = 0; i < 8; i++) {
                int idx = tid + i*256;
                int c = idx >> 3, col = (idx & 7)*8;
                cp_async16(sbase + (unsigned)(KS_OFF + st*KS_SZ + c*KS_LD + col)*2u,
                           Kg + (size_t)c*NPOS + j0 + col);
                cp_async16(sbase + (unsigned)(VS_OFF + st*VS_SZ + c*KS_LD + col)*2u,
                           Vg + (size_t)c*NPOS + j0 + col);
            }
        }
        cp_commit();
    }

    // ---- epilogue: normalize, stage [i][c] in SMEM (reuse Q region), coalesced store
    float inv0 = 1.f / l0, inv1 = 1.f / l1;
    int g = lane >> 2, t = lane & 3;
    #pragma unroll
    for (int nt = 0; nt < 32; nt++) {
        int c = nt*8 + 2*t;
        __half2 h0 = __floats2half2_rn(oacc[nt][0]*inv0, oacc[nt][1]*inv0);
        __half2 h1 = __floats2half2_rn(oacc[nt][2]*inv1, oacc[nt][3]*inv1);
        *reinterpret_cast<__half2*>(&smem[(warp*16 + g    )*OS_LD + c]) = h0;
        *reinterpret_cast<__half2*>(&smem[(warp*16 + g + 8)*OS_LD + c]) = h1;
    }
    __syncthreads();
    __half* Ob = Og + (size_t)b*sX + (size_t)i0*CH;
    #pragma unroll
    for (int i = 0; i < 16; i++) {
        int idx = tid + i*256;
        int row = idx >> 5, col = (idx & 31)*8;
        *reinterpret_cast<uint4*>(&Ob[(size_t)row*CH + col]) =
            *reinterpret_cast<uint4*>(&smem[row*OS_LD + col]);
    }
}

// ---------------- launcher ----------------
extern "C" void kernel_launch(void* const* d_in, const int* in_sizes, int n_in,
                              void* d_out, int out_size) {
    const float* x     = (const float*)d_in[0];
    const float* gamma = (const float*)d_in[1];
    const float* beta  = (const float*)d_in[2];
    const float* wq    = (const float*)d_in[3];
    const float* bq    = (const float*)d_in[4];
    const float* wk    = (const float*)d_in[5];
    const float* bk    = (const float*)d_in[6];
    const float* wv    = (const float*)d_in[7];
    const float* bv    = (const float*)d_in[8];
    const float* wp    = (const float*)d_in[9];
    const float* bp    = (const float*)d_in[10];
    float* out = (float*)d_out;

    __half *xn, *q, *k, *v, *o, *w;
    cudaGetSymbolAddress((void**)&xn, h_xn);
    cudaGetSymbolAddress((void**)&q,  h_q);
    cudaGetSymbolAddress((void**)&k,  h_k);
    cudaGetSymbolAddress((void**)&v,  h_v);
    cudaGetSymbolAddress((void**)&o,  h_o);
    cudaGetSymbolAddress((void**)&w,  h_w);

    static bool attr_set = false;
    if (!attr_set) {
        cudaFuncSetAttribute(flash_kernel,
                             cudaFuncAttributeMaxDynamicSharedMemorySize, FLASH_SMEM);
        attr_set = true;
    }

    // 0. weights fp32 -> fp16
    wcvt_kernel<<<CH*CH/256, 256>>>(wq, wk, wv, wp);

    // 1. GroupNorm -> fp16 xn
    gn_partial_kernel<<<BATCH*NGRP*GSPLIT, 256>>>(x);
    gn_stats_kernel<<<1, 64>>>();
    gn_norm_kernel<<<(BATCH*CH*NPOS)/(256*8), 256>>>(x, gamma, beta);

    const long long sX = (long long)CH * NPOS;

    // 2. Q/K/V projections: W[256,256] x Xn[256,4096] -> fp16 [c][i]
    dim3 gq(NPOS/128, CH/128, BATCH);
    hgemm_kernel<false,false,false><<<gq,256>>>(w,           xn, q, CH, CH, NPOS, NPOS,
                                                0, sX, sX, 1.f, bq, nullptr, 0);
    hgemm_kernel<false,false,false><<<gq,256>>>(w +   CH*CH, xn, k, CH, CH, NPOS, NPOS,
                                                0, sX, sX, 1.f, bk, nullptr, 0);
    hgemm_kernel<false,false,false><<<gq,256>>>(w + 2*CH*CH, xn, v, CH, CH, NPOS, NPOS,
                                                0, sX, sX, 1.f, bv, nullptr, 0);

    // 3-5. fused flash attention -> o [i][c]
    dim3 gf(NPOS/BR, BATCH);
    flash_kernel<<<gf, 256, FLASH_SMEM>>>(q, k, v, o);

    // 6. out = Wp*O + bp + x (residual, fp32 out); O is n-major (BNM)
    hgemm_kernel<false,true,true><<<gq,256>>>(w + 3*CH*CH, o, out, CH, CH, CH, NPOS,
                                              0, sX, sX, 1.f, bp, x, sX);
}